// round 7
// baseline (speedup 1.0000x reference)
#include <cuda_runtime.h>

// B=8, L=512, E=H=1024, K=16, 4H=4096
typedef unsigned long long u64;

// ---------------- scratch (static __device__; no allocations) ----------------
__device__ float g_G[2][4096][4096];        // input projections + bias, [dir][b*512+pos][4H]
__device__ float g_hbuf[2][2][8][1024];     // double-buffered h: [buf][dir][b][n]
__device__ float g_c[2][8][1024];           // cell state [dir][b][n]
__device__ float g_hout[2][8][512][1024];   // h outputs at original positions
__device__ float g_emit[8][512][16];        // emissions

// ---------------- packed f32x2 helpers ----------------
__device__ __forceinline__ u64 pack2(float x, float y){
    u64 r;
    asm("mov.b64 %0, {%1, %2};" : "=l"(r)
        : "r"(__float_as_uint(x)), "r"(__float_as_uint(y)));
    return r;
}
__device__ __forceinline__ void unpack2(u64 v, float &x, float &y){
    unsigned a, b;
    asm("mov.b64 {%0, %1}, %2;" : "=r"(a), "=r"(b) : "l"(v));
    x = __uint_as_float(a); y = __uint_as_float(b);
}
__device__ __forceinline__ void ffma2(u64 &acc, u64 a, u64 b){
    asm("fma.rn.f32x2 %0, %1, %2, %0;" : "+l"(acc) : "l"(a), "l"(b));
}
__device__ __forceinline__ u64 addf2(u64 a, u64 b){
    u64 r;
    asm("add.rn.f32x2 %0, %1, %2;" : "=l"(r) : "l"(a), "l"(b));
    return r;
}
__device__ __forceinline__ u64 shfl_xor_u64(u64 v, int m){
    unsigned lo = (unsigned)(v & 0xffffffffull);
    unsigned hi = (unsigned)(v >> 32);
    lo = __shfl_xor_sync(0xffffffffu, lo, m);
    hi = __shfl_xor_sync(0xffffffffu, hi, m);
    return ((u64)hi << 32) | (u64)lo;
}
__device__ __forceinline__ float fast_sigmoid(float x){
    return 1.f / (1.f + __expf(-x));
}
__device__ __forceinline__ float fast_tanh(float x){
    return 1.f - 2.f / (__expf(2.f * x) + 1.f);   // stable at both infinities
}

// ---------------- init: zero h(buf0) and c ----------------
__global__ void init_kernel(){
    int i = blockIdx.x * 256 + threadIdx.x;
    float* h0 = &g_hbuf[0][0][0][0];   // buffer 0 = first 2*8*1024 floats
    float* c0 = &g_c[0][0][0];
    for (int idx = i; idx < 16384; idx += 64 * 256){
        h0[idx] = 0.f;
        c0[idx] = 0.f;
    }
}

// ---------------- Phase A: G = X @ W_ih^T + b (both directions) ----------------
// X: (4096,1024) row-major, W: (4096,1024) row-major (NT), out 4096x4096.
// 64x64 block tile, K-tile 32, 256 threads, 4x4 microtile with f32x2 packing.
__global__ __launch_bounds__(256) void proj_gemm(
    const float* __restrict__ x,
    const float* __restrict__ Wf, const float* __restrict__ bf,
    const float* __restrict__ Wb, const float* __restrict__ bb)
{
    __shared__ float As[32][68];   // [k][row]
    __shared__ float Bs[32][68];
    const int dir = blockIdx.z;
    const float* W    = dir ? Wb : Wf;
    const float* bias = dir ? bb : bf;
    const int tid = threadIdx.x;
    const int mBase = blockIdx.y << 6;
    const int nBase = blockIdx.x << 6;
    const int lrow = tid >> 2;          // 0..63
    const int lk   = (tid & 3) << 3;    // 0,8,16,24
    const int tx = tid & 15;
    const int ty = tid >> 4;

    u64 acc[4][2];
#pragma unroll
    for (int i = 0; i < 4; ++i){ acc[i][0] = 0ull; acc[i][1] = 0ull; }

    const float* xp = x + (size_t)(mBase + lrow) * 1024 + lk;
    const float* wp = W + (size_t)(nBase + lrow) * 1024 + lk;

    for (int kt = 0; kt < 32; ++kt){
        float4 xa0 = *(const float4*)(xp + kt * 32);
        float4 xa1 = *(const float4*)(xp + kt * 32 + 4);
        float4 wa0 = *(const float4*)(wp + kt * 32);
        float4 wa1 = *(const float4*)(wp + kt * 32 + 4);
        __syncthreads();
        As[lk + 0][lrow] = xa0.x; As[lk + 1][lrow] = xa0.y;
        As[lk + 2][lrow] = xa0.z; As[lk + 3][lrow] = xa0.w;
        As[lk + 4][lrow] = xa1.x; As[lk + 5][lrow] = xa1.y;
        As[lk + 6][lrow] = xa1.z; As[lk + 7][lrow] = xa1.w;
        Bs[lk + 0][lrow] = wa0.x; Bs[lk + 1][lrow] = wa0.y;
        Bs[lk + 2][lrow] = wa0.z; Bs[lk + 3][lrow] = wa0.w;
        Bs[lk + 4][lrow] = wa1.x; Bs[lk + 5][lrow] = wa1.y;
        Bs[lk + 6][lrow] = wa1.z; Bs[lk + 7][lrow] = wa1.w;
        __syncthreads();
#pragma unroll
        for (int kk = 0; kk < 32; ++kk){
            float4 a = *(const float4*)&As[kk][ty << 2];
            float4 b = *(const float4*)&Bs[kk][tx << 2];
            u64 b01 = pack2(b.x, b.y);
            u64 b23 = pack2(b.z, b.w);
            u64 a0 = pack2(a.x, a.x), a1 = pack2(a.y, a.y);
            u64 a2 = pack2(a.z, a.z), a3 = pack2(a.w, a.w);
            ffma2(acc[0][0], a0, b01); ffma2(acc[0][1], a0, b23);
            ffma2(acc[1][0], a1, b01); ffma2(acc[1][1], a1, b23);
            ffma2(acc[2][0], a2, b01); ffma2(acc[2][1], a2, b23);
            ffma2(acc[3][0], a3, b01); ffma2(acc[3][1], a3, b23);
        }
    }

    const int ncol = nBase + (tx << 2);
    float4 bv = *(const float4*)(bias + ncol);
#pragma unroll
    for (int i = 0; i < 4; ++i){
        float v0, v1, v2, v3;
        unpack2(acc[i][0], v0, v1);
        unpack2(acc[i][1], v2, v3);
        float4 o = make_float4(v0 + bv.x, v1 + bv.y, v2 + bv.z, v3 + bv.w);
        int m = mBase + (ty << 2) + i;
        *(float4*)(&g_G[dir][m][ncol]) = o;
    }
}

// ---------------- Phase B: one LSTM step (both directions) ----------------
// grid = 128 blocks (64 per dir), 256 threads. Block owns 16 hidden units;
// each warp owns 2 units x 4 gates x 8 batches (batches packed in f32x2).
__global__ __launch_bounds__(256) void lstm_step(
    int t,
    const float* __restrict__ Whf, const float* __restrict__ Whb,
    const int* __restrict__ lengths)
{
    __shared__ float2 hs[4][1024];   // [batch-pair][k] = (h[2p][k], h[2p+1][k])
    const int dir = blockIdx.x >> 6;
    const int ub  = (blockIdx.x & 63) << 4;
    const float* Wh = dir ? Whb : Whf;
    const int tid = threadIdx.x;
    const int rbuf = t & 1, wbuf = rbuf ^ 1;

    const float* hsrc = &g_hbuf[rbuf][dir][0][0];   // [8][1024]
    for (int idx = tid; idx < 4096; idx += 256){
        int p = idx >> 10, k = idx & 1023;
        hs[p][k] = make_float2(hsrc[(p << 11) + k], hsrc[(p << 11) + 1024 + k]);
    }
    __syncthreads();

    const int w = tid >> 5, lane = tid & 31;
    const int n0 = ub + (w << 1);

    const float* wr[8];
#pragma unroll
    for (int r = 0; r < 8; ++r){
        int row = ((r >> 1) << 10) + n0 + (r & 1);  // gate=r>>1, unit=r&1
        wr[r] = Wh + (size_t)row * 1024;
    }

    u64 acc[8][4];
#pragma unroll
    for (int r = 0; r < 8; ++r){
        acc[r][0] = 0ull; acc[r][1] = 0ull; acc[r][2] = 0ull; acc[r][3] = 0ull;
    }

#pragma unroll 1
    for (int c = 0; c < 8; ++c){
        int k = (c << 7) + (lane << 2);
        u64 hk[4][4];
#pragma unroll
        for (int p = 0; p < 4; ++p){
            ulonglong2 u0 = *(const ulonglong2*)&hs[p][k];
            ulonglong2 u1 = *(const ulonglong2*)&hs[p][k + 2];
            hk[p][0] = u0.x; hk[p][1] = u0.y; hk[p][2] = u1.x; hk[p][3] = u1.y;
        }
#pragma unroll
        for (int r = 0; r < 8; ++r){
            float4 w4 = *(const float4*)(wr[r] + k);
            u64 w0 = pack2(w4.x, w4.x), w1 = pack2(w4.y, w4.y);
            u64 w2 = pack2(w4.z, w4.z), w3 = pack2(w4.w, w4.w);
#pragma unroll
            for (int p = 0; p < 4; ++p){
                ffma2(acc[r][p], w0, hk[p][0]);
                ffma2(acc[r][p], w1, hk[p][1]);
                ffma2(acc[r][p], w2, hk[p][2]);
                ffma2(acc[r][p], w3, hk[p][3]);
            }
        }
    }

    // butterfly reduce across 32 lanes (packed pairwise)
#pragma unroll
    for (int r = 0; r < 8; ++r){
#pragma unroll
        for (int p = 0; p < 4; ++p){
            u64 v = acc[r][p];
            v = addf2(v, shfl_xor_u64(v, 16));
            v = addf2(v, shfl_xor_u64(v, 8));
            v = addf2(v, shfl_xor_u64(v, 4));
            v = addf2(v, shfl_xor_u64(v, 2));
            v = addf2(v, shfl_xor_u64(v, 1));
            acc[r][p] = v;
        }
    }

    // lanes 0..15 finish (u,b) = (lane>>3, lane&7)
    if (lane < 16){
        const int u = lane >> 3, b = lane & 7;
        const int p = b >> 1, half = b & 1;
        float gsum[4];
#pragma unroll
        for (int g = 0; g < 4; ++g){
            float lo, hi;
            unpack2(acc[(g << 1) + u][p], lo, hi);
            gsum[g] = half ? hi : lo;
        }
        const int n = n0 + u;
        const int lb = lengths[b];
        if (t < lb){
            int pos = dir ? (lb - 1 - t) : t;
            const float* Gp = &g_G[dir][(b << 9) + pos][0];
            float gi = gsum[0] + Gp[n];
            float gf = gsum[1] + Gp[1024 + n];
            float gg = gsum[2] + Gp[2048 + n];
            float go = gsum[3] + Gp[3072 + n];
            float si = fast_sigmoid(gi);
            float sf = fast_sigmoid(gf);
            float tg = fast_tanh(gg);
            float so = fast_sigmoid(go);
            float cn = sf * g_c[dir][b][n] + si * tg;
            float hn = so * fast_tanh(cn);
            g_c[dir][b][n] = cn;
            g_hbuf[wbuf][dir][b][n] = hn;
            g_hout[dir][b][pos][n] = hn;
        } else {
            g_hbuf[wbuf][dir][b][n] = g_hbuf[rbuf][dir][b][n];  // carry state
        }
    }
}

// ---------------- Phase C1: emissions ----------------
// grid (512,8), 128 threads: block = (t,b); emit[b][t][k] = [hf,hb].W_emit[k]+b_emit[k]
__global__ void emit_kernel(const int* __restrict__ lengths,
                            const float* __restrict__ We,
                            const float* __restrict__ be)
{
    const int t = blockIdx.x, b = blockIdx.y;
    if (t >= lengths[b]) return;
    __shared__ float h[2048];
    const int tid = threadIdx.x;
    const float* hf = &g_hout[0][b][t][0];
    const float* hb = &g_hout[1][b][t][0];
    for (int j = tid; j < 1024; j += 128){
        h[j]        = hf[j];
        h[1024 + j] = hb[j];
    }
    __syncthreads();
    const int k = tid >> 3, sub = tid & 7;
    const float* wk = We + (k << 11);
    float s = 0.f;
    for (int j = (sub << 2); j < 2048; j += 32){
        float4 wv = *(const float4*)(wk + j);
        float4 hv = *(const float4*)(&h[j]);
        s += wv.x * hv.x + wv.y * hv.y + wv.z * hv.z + wv.w * hv.w;
    }
    s += __shfl_xor_sync(0xffffffffu, s, 4);
    s += __shfl_xor_sync(0xffffffffu, s, 2);
    s += __shfl_xor_sync(0xffffffffu, s, 1);
    if (sub == 0) g_emit[b][t][k] = s + be[k];
}

// ---------------- Phase C2: CRF gold score + forward algorithm ----------------
__global__ void crf_kernel(const int* __restrict__ tags,
                           const int* __restrict__ lengths,
                           const float* __restrict__ trans,
                           float* __restrict__ out)
{
    __shared__ float T[16][16];
    const int tid = threadIdx.x;
    T[tid >> 4][tid & 15] = trans[tid];
    __syncthreads();

    const int b = tid >> 5, lane = tid & 31;
    const int lb = lengths[b];
    const int* tg = tags + (b << 9);

    float sc = 0.f;
    for (int tt = lane; tt < lb; tt += 32){
        sc += g_emit[b][tt][tg[tt]];
        if (tt >= 1) sc += T[tg[tt - 1]][tg[tt]];
    }
#pragma unroll
    for (int o = 16; o; o >>= 1) sc += __shfl_xor_sync(0xffffffffu, sc, o);

    // forward algorithm: lane j (<16) holds d[j]
    const int j = lane & 15;
    float d = (lane < 16) ? g_emit[b][0][j] : -3e38f;
    for (int tt = 1; tt < lb; ++tt){
        float v[16];
        float mx = -3e38f;
#pragma unroll
        for (int i = 0; i < 16; ++i){
            float di = __shfl_sync(0xffffffffu, d, i);
            v[i] = di + T[i][j];
            mx = fmaxf(mx, v[i]);
        }
        float ssum = 0.f;
#pragma unroll
        for (int i = 0; i < 16; ++i) ssum += __expf(v[i] - mx);
        float nd = mx + __logf(ssum) + g_emit[b][tt][j];
        if (lane < 16) d = nd;
    }

    float mz = d;
#pragma unroll
    for (int o = 8; o; o >>= 1) mz = fmaxf(mz, __shfl_xor_sync(0xffffffffu, mz, o));
    float zs = __expf(d - mz);
#pragma unroll
    for (int o = 8; o; o >>= 1) zs += __shfl_xor_sync(0xffffffffu, zs, o);
    float logZ = mz + __logf(zs);

    if (lane == 0) out[b] = logZ - sc;
}

// ---------------- launch ----------------
extern "C" void kernel_launch(void* const* d_in, const int* in_sizes, int n_in,
                              void* d_out, int out_size)
{
    (void)in_sizes; (void)n_in; (void)out_size;
    const float* x    = (const float*)d_in[0];
    const int*   tags = (const int*)  d_in[1];
    const int*   lens = (const int*)  d_in[2];
    const float* Wihf = (const float*)d_in[3];
    const float* Whhf = (const float*)d_in[4];
    const float* bf_  = (const float*)d_in[5];
    const float* Wihb = (const float*)d_in[6];
    const float* Whhb = (const float*)d_in[7];
    const float* bb_  = (const float*)d_in[8];
    const float* We   = (const float*)d_in[9];
    const float* be   = (const float*)d_in[10];
    const float* tr   = (const float*)d_in[11];
    float* out = (float*)d_out;

    init_kernel<<<64, 256>>>();
    proj_gemm<<<dim3(64, 64, 2), 256>>>(x, Wihf, bf_, Wihb, bb_);
    for (int t = 0; t < 512; ++t)
        lstm_step<<<128, 256>>>(t, Whhf, Whhb, lens);
    emit_kernel<<<dim3(512, 8), 128>>>(lens, We, be);
    crf_kernel<<<1, 256>>>(tags, lens, tr, out);
}

// round 8
// speedup vs baseline: 1.1970x; 1.1970x over previous
#include <cuda_runtime.h>

// B=8, L=512, E=H=1024, K=16, 4H=4096
typedef unsigned long long u64;

#define NBLK 128   // persistent grid: must be <= SM count (148) for residency

// ---------------- scratch (static __device__; no allocations) ----------------
__device__ float g_G[2][4096][4096];        // input projections + bias, [dir][b*512+pos][4H]
__device__ float g_hbuf[2][2][8][1024];     // double-buffered h: [buf][dir][b][n]
__device__ float g_hout[2][8][512][1024];   // h outputs at original positions
__device__ float g_emit[8][512][16];        // emissions
__device__ unsigned g_bar_cnt, g_bar_gen;   // grid barrier state

// ---------------- packed f32x2 helpers ----------------
__device__ __forceinline__ u64 pack2(float x, float y){
    u64 r;
    asm("mov.b64 %0, {%1, %2};" : "=l"(r)
        : "r"(__float_as_uint(x)), "r"(__float_as_uint(y)));
    return r;
}
__device__ __forceinline__ u64 pack1(float x){
    u64 r;
    asm("mov.b64 %0, {%1, %1};" : "=l"(r) : "r"(__float_as_uint(x)));
    return r;
}
__device__ __forceinline__ void unpack2(u64 v, float &x, float &y){
    unsigned a, b;
    asm("mov.b64 {%0, %1}, %2;" : "=r"(a), "=r"(b) : "l"(v));
    x = __uint_as_float(a); y = __uint_as_float(b);
}
__device__ __forceinline__ void ffma2(u64 &acc, u64 a, u64 b){
    asm("fma.rn.f32x2 %0, %1, %2, %0;" : "+l"(acc) : "l"(a), "l"(b));
}
__device__ __forceinline__ u64 addf2(u64 a, u64 b){
    u64 r;
    asm("add.rn.f32x2 %0, %1, %2;" : "=l"(r) : "l"(a), "l"(b));
    return r;
}
__device__ __forceinline__ u64 shfl_xor_u64(u64 v, int m){
    unsigned lo = (unsigned)(v & 0xffffffffull);
    unsigned hi = (unsigned)(v >> 32);
    lo = __shfl_xor_sync(0xffffffffu, lo, m);
    hi = __shfl_xor_sync(0xffffffffu, hi, m);
    return ((u64)hi << 32) | (u64)lo;
}
__device__ __forceinline__ float fast_sigmoid(float x){
    return 1.f / (1.f + __expf(-x));
}
__device__ __forceinline__ float fast_tanh(float x){
    return 1.f - 2.f / (__expf(2.f * x) + 1.f);   // stable at both infinities
}

// ---------------- grid barrier (all NBLK blocks resident) ----------------
__device__ __forceinline__ void grid_sync(unsigned gen){
    __threadfence();
    __syncthreads();
    if (threadIdx.x == 0){
        unsigned old = atomicAdd(&g_bar_cnt, 1u);
        if (old == NBLK - 1u){
            atomicExch(&g_bar_cnt, 0u);
            __threadfence();
            atomicExch(&g_bar_gen, gen + 1u);
        } else {
            unsigned v;
            do {
                asm volatile("ld.global.cg.u32 %0, [%1];" : "=r"(v) : "l"(&g_bar_gen));
            } while (v == gen);
        }
    }
    __syncthreads();
}

__global__ void init_bar(){
    if (threadIdx.x == 0){ g_bar_cnt = 0u; g_bar_gen = 0u; }
}

// ---------------- Phase A: G = X @ W_ih^T + b (both directions) ----------------
__global__ __launch_bounds__(256) void proj_gemm(
    const float* __restrict__ x,
    const float* __restrict__ Wf, const float* __restrict__ bf,
    const float* __restrict__ Wb, const float* __restrict__ bb)
{
    __shared__ float As[32][68];   // [k][row]
    __shared__ float Bs[32][68];
    const int dir = blockIdx.z;
    const float* W    = dir ? Wb : Wf;
    const float* bias = dir ? bb : bf;
    const int tid = threadIdx.x;
    const int mBase = blockIdx.y << 6;
    const int nBase = blockIdx.x << 6;
    const int lrow = tid >> 2;          // 0..63
    const int lk   = (tid & 3) << 3;    // 0,8,16,24
    const int tx = tid & 15;
    const int ty = tid >> 4;

    u64 acc[4][2];
#pragma unroll
    for (int i = 0; i < 4; ++i){ acc[i][0] = 0ull; acc[i][1] = 0ull; }

    const float* xp = x + (size_t)(mBase + lrow) * 1024 + lk;
    const float* wp = W + (size_t)(nBase + lrow) * 1024 + lk;

    for (int kt = 0; kt < 32; ++kt){
        float4 xa0 = *(const float4*)(xp + kt * 32);
        float4 xa1 = *(const float4*)(xp + kt * 32 + 4);
        float4 wa0 = *(const float4*)(wp + kt * 32);
        float4 wa1 = *(const float4*)(wp + kt * 32 + 4);
        __syncthreads();
        As[lk + 0][lrow] = xa0.x; As[lk + 1][lrow] = xa0.y;
        As[lk + 2][lrow] = xa0.z; As[lk + 3][lrow] = xa0.w;
        As[lk + 4][lrow] = xa1.x; As[lk + 5][lrow] = xa1.y;
        As[lk + 6][lrow] = xa1.z; As[lk + 7][lrow] = xa1.w;
        Bs[lk + 0][lrow] = wa0.x; Bs[lk + 1][lrow] = wa0.y;
        Bs[lk + 2][lrow] = wa0.z; Bs[lk + 3][lrow] = wa0.w;
        Bs[lk + 4][lrow] = wa1.x; Bs[lk + 5][lrow] = wa1.y;
        Bs[lk + 6][lrow] = wa1.z; Bs[lk + 7][lrow] = wa1.w;
        __syncthreads();
#pragma unroll
        for (int kk = 0; kk < 32; ++kk){
            float4 a = *(const float4*)&As[kk][ty << 2];
            float4 b = *(const float4*)&Bs[kk][tx << 2];
            u64 b01 = pack2(b.x, b.y);
            u64 b23 = pack2(b.z, b.w);
            u64 a0 = pack1(a.x), a1 = pack1(a.y);
            u64 a2 = pack1(a.z), a3 = pack1(a.w);
            ffma2(acc[0][0], a0, b01); ffma2(acc[0][1], a0, b23);
            ffma2(acc[1][0], a1, b01); ffma2(acc[1][1], a1, b23);
            ffma2(acc[2][0], a2, b01); ffma2(acc[2][1], a2, b23);
            ffma2(acc[3][0], a3, b01); ffma2(acc[3][1], a3, b23);
        }
    }

    const int ncol = nBase + (tx << 2);
    float4 bv = *(const float4*)(bias + ncol);
#pragma unroll
    for (int i = 0; i < 4; ++i){
        float v0, v1, v2, v3;
        unpack2(acc[i][0], v0, v1);
        unpack2(acc[i][1], v2, v3);
        float4 o = make_float4(v0 + bv.x, v1 + bv.y, v2 + bv.z, v3 + bv.w);
        int m = mBase + (ty << 2) + i;
        *(float4*)(&g_G[dir][m][ncol]) = o;
    }
}

// ---------------- Phase B: persistent bidirectional LSTM ----------------
// 128 blocks x 512 threads. Block: one dir, 16 hidden units (1 per warp).
// Gates i,f,g weight rows live in smem (192 KB fp32); gate-o row streams from L2.
// c and h live in registers; h crosses blocks via L2 (.cg) + grid barrier.
#define SMEM_PERSIST (48*1024*4 + 4*1024*8)   // 196608 + 32768 = 229376 B

__global__ __launch_bounds__(512) void lstm_persist(
    const float* __restrict__ Whf, const float* __restrict__ Whb,
    const int* __restrict__ lengths)
{
    extern __shared__ char smraw[];
    float*  ws = (float*)smraw;                       // [48][1024]
    float2* hs = (float2*)(smraw + 48*1024*4);        // [4][1024]: (h[2p][k], h[2p+1][k])

    const int blk = blockIdx.x;
    const int dir = blk >> 6;
    const int ub  = (blk & 63) << 4;
    const float* Wh = dir ? Whb : Whf;
    const int tid  = threadIdx.x;
    const int w    = tid >> 5;      // warp 0..15 -> unit
    const int lane = tid & 31;
    const int n    = ub + w;        // this warp's hidden unit

    // preload 48 weight rows (gates 0..2 for all 16 units) into smem, fp32
    for (int i = tid; i < 48 * 256; i += 512){
        int lr = i >> 8, q = (i & 255) << 2;
        int grow = ((lr >> 4) << 10) + ub + (lr & 15);   // gate*1024 + unit
        float4 v = *(const float4*)(Wh + (size_t)grow * 1024 + q);
        *(float4*)&ws[lr * 1024 + q] = v;
    }
    const float* wo = Wh + (size_t)(3 * 1024 + n) * 1024;  // gate-o row, from L2

    const int b  = lane & 7;
    const int lb = lengths[b];
    float hreg = 0.f, creg = 0.f;

    // zero the t=0 read buffer of h
    if (lane < 8) g_hbuf[0][dir][b][n] = 0.f;

    unsigned gen = 0;
    grid_sync(gen); ++gen;

    const float* wr0 = &ws[( 0 + w) * 1024];
    const float* wr1 = &ws[(16 + w) * 1024];
    const float* wr2 = &ws[(32 + w) * 1024];

    for (int t = 0; t < 512; ++t){
        const int rbuf = t & 1, wbuf = rbuf ^ 1;

        // prefetch this step's G row entries (DRAM latency hidden by dot product)
        float q0 = 0.f, q1 = 0.f, q2 = 0.f, q3 = 0.f;
        const int pos = dir ? (lb - 1 - t) : t;
        const bool act = (lane < 8) && (t < lb);
        if (act){
            const float* Gp = &g_G[dir][(b << 9) + pos][0];
            q0 = Gp[n]; q1 = Gp[1024 + n]; q2 = Gp[2048 + n]; q3 = Gp[3072 + n];
        }

        // stage h_{t-1} (bypass L1: written by other SMs last step)
        const float* hb0 = &g_hbuf[rbuf][dir][0][0];
        for (int idx = tid; idx < 4096; idx += 512){
            int p = idx >> 10, k = idx & 1023;
            float a0 = __ldcg(hb0 + (p << 11) + k);
            float a1 = __ldcg(hb0 + (p << 11) + 1024 + k);
            hs[(p << 10) + k] = make_float2(a0, a1);
        }
        __syncthreads();

        u64 acc[4][4];
#pragma unroll
        for (int r = 0; r < 4; ++r){
            acc[r][0] = 0ull; acc[r][1] = 0ull; acc[r][2] = 0ull; acc[r][3] = 0ull;
        }

#pragma unroll
        for (int c = 0; c < 8; ++c){
            const int k = (c << 7) + (lane << 2);
            u64 hk[4][4];
#pragma unroll
            for (int p = 0; p < 4; ++p){
                ulonglong2 u0 = *(const ulonglong2*)&hs[(p << 10) + k];
                ulonglong2 u1 = *(const ulonglong2*)&hs[(p << 10) + k + 2];
                hk[p][0] = u0.x; hk[p][1] = u0.y; hk[p][2] = u1.x; hk[p][3] = u1.y;
            }
#pragma unroll
            for (int r = 0; r < 4; ++r){
                float4 w4 = (r == 0) ? *(const float4*)(wr0 + k)
                          : (r == 1) ? *(const float4*)(wr1 + k)
                          : (r == 2) ? *(const float4*)(wr2 + k)
                                     : *(const float4*)(wo  + k);
                u64 w0 = pack1(w4.x), w1 = pack1(w4.y);
                u64 w2 = pack1(w4.z), w3 = pack1(w4.w);
#pragma unroll
                for (int p = 0; p < 4; ++p){
                    ffma2(acc[r][p], w0, hk[p][0]);
                    ffma2(acc[r][p], w1, hk[p][1]);
                    ffma2(acc[r][p], w2, hk[p][2]);
                    ffma2(acc[r][p], w3, hk[p][3]);
                }
            }
        }

        // butterfly reduce over 32 lanes (packed batch pairs)
#pragma unroll
        for (int r = 0; r < 4; ++r){
#pragma unroll
            for (int p = 0; p < 4; ++p){
                u64 v = acc[r][p];
                v = addf2(v, shfl_xor_u64(v, 16));
                v = addf2(v, shfl_xor_u64(v,  8));
                v = addf2(v, shfl_xor_u64(v,  4));
                v = addf2(v, shfl_xor_u64(v,  2));
                v = addf2(v, shfl_xor_u64(v,  1));
                acc[r][p] = v;
            }
        }

        // lanes 0..7 finish their batch b = lane for unit n
        if (lane < 8){
            const int p = b >> 1, half = b & 1;
            float gs[4];
#pragma unroll
            for (int r = 0; r < 4; ++r){
                float lo, hi;
                unpack2(acc[r][p], lo, hi);
                gs[r] = half ? hi : lo;
            }
            if (t < lb){
                float gi = gs[0] + q0;
                float gf = gs[1] + q1;
                float gg = gs[2] + q2;
                float go = gs[3] + q3;
                float si = fast_sigmoid(gi);
                float sf = fast_sigmoid(gf);
                float tg = fast_tanh(gg);
                float so = fast_sigmoid(go);
                creg = sf * creg + si * tg;
                hreg = so * fast_tanh(creg);
                g_hout[dir][b][pos][n] = hreg;
            }
            g_hbuf[wbuf][dir][b][n] = hreg;   // carry-forward when masked
        }

        if (t < 511){ grid_sync(gen); ++gen; }
    }
}

// ---------------- Phase C1: emissions ----------------
__global__ void emit_kernel(const int* __restrict__ lengths,
                            const float* __restrict__ We,
                            const float* __restrict__ be)
{
    const int t = blockIdx.x, b = blockIdx.y;
    if (t >= lengths[b]) return;
    __shared__ float h[2048];
    const int tid = threadIdx.x;
    const float* hf = &g_hout[0][b][t][0];
    const float* hb = &g_hout[1][b][t][0];
    for (int j = tid; j < 1024; j += 128){
        h[j]        = hf[j];
        h[1024 + j] = hb[j];
    }
    __syncthreads();
    const int k = tid >> 3, sub = tid & 7;
    const float* wk = We + (k << 11);
    float s = 0.f;
    for (int j = (sub << 2); j < 2048; j += 32){
        float4 wv = *(const float4*)(wk + j);
        float4 hv = *(const float4*)(&h[j]);
        s += wv.x * hv.x + wv.y * hv.y + wv.z * hv.z + wv.w * hv.w;
    }
    s += __shfl_xor_sync(0xffffffffu, s, 4);
    s += __shfl_xor_sync(0xffffffffu, s, 2);
    s += __shfl_xor_sync(0xffffffffu, s, 1);
    if (sub == 0) g_emit[b][t][k] = s + be[k];
}

// ---------------- Phase C2: CRF gold score + forward algorithm ----------------
__global__ void crf_kernel(const int* __restrict__ tags,
                           const int* __restrict__ lengths,
                           const float* __restrict__ trans,
                           float* __restrict__ out)
{
    __shared__ float T[16][16];
    const int tid = threadIdx.x;
    T[tid >> 4][tid & 15] = trans[tid];
    __syncthreads();

    const int b = tid >> 5, lane = tid & 31;
    const int lb = lengths[b];
    const int* tg = tags + (b << 9);

    float sc = 0.f;
    for (int tt = lane; tt < lb; tt += 32){
        sc += g_emit[b][tt][tg[tt]];
        if (tt >= 1) sc += T[tg[tt - 1]][tg[tt]];
    }
#pragma unroll
    for (int o = 16; o; o >>= 1) sc += __shfl_xor_sync(0xffffffffu, sc, o);

    const int j = lane & 15;
    float d = (lane < 16) ? g_emit[b][0][j] : -3e38f;
    for (int tt = 1; tt < lb; ++tt){
        float v[16];
        float mx = -3e38f;
#pragma unroll
        for (int i = 0; i < 16; ++i){
            float di = __shfl_sync(0xffffffffu, d, i);
            v[i] = di + T[i][j];
            mx = fmaxf(mx, v[i]);
        }
        float ssum = 0.f;
#pragma unroll
        for (int i = 0; i < 16; ++i) ssum += __expf(v[i] - mx);
        float nd = mx + __logf(ssum) + g_emit[b][tt][j];
        if (lane < 16) d = nd;
    }

    float mz = d;
#pragma unroll
    for (int o = 8; o; o >>= 1) mz = fmaxf(mz, __shfl_xor_sync(0xffffffffu, mz, o));
    float zs = __expf(d - mz);
#pragma unroll
    for (int o = 8; o; o >>= 1) zs += __shfl_xor_sync(0xffffffffu, zs, o);
    float logZ = mz + __logf(zs);

    if (lane == 0) out[b] = logZ - sc;
}

// ---------------- launch ----------------
extern "C" void kernel_launch(void* const* d_in, const int* in_sizes, int n_in,
                              void* d_out, int out_size)
{
    (void)in_sizes; (void)n_in; (void)out_size;
    const float* x    = (const float*)d_in[0];
    const int*   tags = (const int*)  d_in[1];
    const int*   lens = (const int*)  d_in[2];
    const float* Wihf = (const float*)d_in[3];
    const float* Whhf = (const float*)d_in[4];
    const float* bf_  = (const float*)d_in[5];
    const float* Wihb = (const float*)d_in[6];
    const float* Whhb = (const float*)d_in[7];
    const float* bb_  = (const float*)d_in[8];
    const float* We   = (const float*)d_in[9];
    const float* be   = (const float*)d_in[10];
    const float* tr   = (const float*)d_in[11];
    float* out = (float*)d_out;

    cudaFuncSetAttribute(lstm_persist,
                         cudaFuncAttributeMaxDynamicSharedMemorySize, SMEM_PERSIST);

    init_bar<<<1, 32>>>();
    proj_gemm<<<dim3(64, 64, 2), 256>>>(x, Wihf, bf_, Wihb, bb_);
    lstm_persist<<<NBLK, 512, SMEM_PERSIST>>>(Whhf, Whhb, lens);
    emit_kernel<<<dim3(512, 8), 128>>>(lens, We, be);
    crf_kernel<<<1, 256>>>(tags, lens, tr, out);
}

// round 9
// speedup vs baseline: 1.5309x; 1.2789x over previous
#include <cuda_runtime.h>

// B=8, L=512, E=H=1024, K=16, 4H=4096
typedef unsigned long long u64;

// ---------------- scratch (static __device__; no allocations) ----------------
__device__ float g_G[2][4096][4096];          // input projections + bias
__device__ float g_hpair[2][2][4][1024][2];   // h double-buffered, batch-PAIR interleaved:
                                              // [buf][dir][p][n][half] = h[2p+half][n]
__device__ float g_hout[2][8][512][1024];     // h outputs at original positions
__device__ float g_emit[8][512][16];          // emissions
__device__ unsigned g_cnt[2], g_gen[2];       // per-direction barrier state

// ---------------- packed f32x2 helpers ----------------
__device__ __forceinline__ u64 pack1(float x){
    u64 r;
    asm("mov.b64 %0, {%1, %1};" : "=l"(r) : "r"(__float_as_uint(x)));
    return r;
}
__device__ __forceinline__ void unpack2(u64 v, float &x, float &y){
    unsigned a, b;
    asm("mov.b64 {%0, %1}, %2;" : "=r"(a), "=r"(b) : "l"(v));
    x = __uint_as_float(a); y = __uint_as_float(b);
}
__device__ __forceinline__ void ffma2(u64 &acc, u64 a, u64 b){
    asm("fma.rn.f32x2 %0, %1, %2, %0;" : "+l"(acc) : "l"(a), "l"(b));
}
__device__ __forceinline__ u64 addf2(u64 a, u64 b){
    u64 r;
    asm("add.rn.f32x2 %0, %1, %2;" : "=l"(r) : "l"(a), "l"(b));
    return r;
}
__device__ __forceinline__ u64 shfl_xor_u64(u64 v, int m){
    unsigned lo = (unsigned)(v & 0xffffffffull);
    unsigned hi = (unsigned)(v >> 32);
    lo = __shfl_xor_sync(0xffffffffu, lo, m);
    hi = __shfl_xor_sync(0xffffffffu, hi, m);
    return ((u64)hi << 32) | (u64)lo;
}
__device__ __forceinline__ float fast_sigmoid(float x){
    return 1.f / (1.f + __expf(-x));
}
__device__ __forceinline__ float fast_tanh(float x){
    return 1.f - 2.f / (__expf(2.f * x) + 1.f);   // stable at both infinities
}

// ---------------- per-direction grid barrier (64 blocks each) ----------------
__device__ __forceinline__ void dir_sync(int dir, unsigned gen){
    __syncthreads();
    if (threadIdx.x == 0){
        unsigned old;
        asm volatile("atom.release.gpu.global.add.u32 %0, [%1], %2;"
                     : "=r"(old) : "l"(&g_cnt[dir]), "r"(1u) : "memory");
        if (old == 63u){
            g_cnt[dir] = 0u;                    // ordered before release-store below
            unsigned nv = gen + 1u;
            asm volatile("st.release.gpu.global.u32 [%0], %1;"
                         :: "l"(&g_gen[dir]), "r"(nv) : "memory");
        } else {
            unsigned v;
            do {
                asm volatile("ld.acquire.gpu.global.u32 %0, [%1];"
                             : "=r"(v) : "l"(&g_gen[dir]) : "memory");
            } while (v == gen);
        }
    }
    __syncthreads();
}

__global__ void init_bar(){
    if (threadIdx.x < 2){ g_cnt[threadIdx.x] = 0u; g_gen[threadIdx.x] = 0u; }
}

// ---------------- Phase A: G = X @ W_ih^T + b (both directions) ----------------
// X: (4096,1024), W: (4096,1024) (NT). Block tile 128(M) x 64(N), K-tile 16.
// Accumulators packed over M-row PAIRS -> A operand loads directly as u64,
// only B needs splats: 16 FFMA2 per kk, fma-pipe bound.
__global__ __launch_bounds__(256) void proj_gemm(
    const float* __restrict__ x,
    const float* __restrict__ Wf, const float* __restrict__ bf,
    const float* __restrict__ Wb, const float* __restrict__ bb)
{
    __shared__ float As[16][136];   // [k][row 0..127], rows 8B-aligned pairs
    __shared__ float Bs[16][72];    // [k][col 0..63]
    const int dir = blockIdx.z;
    const float* W    = dir ? Wb : Wf;
    const float* bias = dir ? bb : bf;
    const int tid = threadIdx.x;
    const int mBase = blockIdx.y << 7;
    const int nBase = blockIdx.x << 6;
    const int tx = tid & 15;        // col group: 4*tx
    const int ty = tid >> 4;        // row group: 8*ty

    const int ar = tid >> 1;            // 0..127
    const int ak = (tid & 1) << 3;      // 0 or 8
    const int br = tid >> 2;            // 0..63
    const int bk = (tid & 3) << 2;      // 0,4,8,12

    const float* xp = x + (size_t)(mBase + ar) * 1024 + ak;
    const float* wp = W + (size_t)(nBase + br) * 1024 + bk;

    u64 acc[4][4];                      // [row-pair i][col j]
#pragma unroll
    for (int i = 0; i < 4; ++i)
#pragma unroll
        for (int j = 0; j < 4; ++j) acc[i][j] = 0ull;

    for (int kt = 0; kt < 64; ++kt){
        float4 a0 = *(const float4*)(xp + kt * 16);
        float4 a1 = *(const float4*)(xp + kt * 16 + 4);
        float4 bv = *(const float4*)(wp + kt * 16);
        __syncthreads();
        As[ak + 0][ar] = a0.x; As[ak + 1][ar] = a0.y;
        As[ak + 2][ar] = a0.z; As[ak + 3][ar] = a0.w;
        As[ak + 4][ar] = a1.x; As[ak + 5][ar] = a1.y;
        As[ak + 6][ar] = a1.z; As[ak + 7][ar] = a1.w;
        Bs[bk + 0][br] = bv.x; Bs[bk + 1][br] = bv.y;
        Bs[bk + 2][br] = bv.z; Bs[bk + 3][br] = bv.w;
        __syncthreads();
#pragma unroll
        for (int kk = 0; kk < 16; ++kk){
            ulonglong2 A0 = *(const ulonglong2*)&As[kk][ty << 3];
            ulonglong2 A1 = *(const ulonglong2*)&As[kk][(ty << 3) + 4];
            u64 ap0 = A0.x, ap1 = A0.y, ap2 = A1.x, ap3 = A1.y;
            float4 b4 = *(const float4*)&Bs[kk][tx << 2];
            u64 s0 = pack1(b4.x), s1 = pack1(b4.y);
            u64 s2 = pack1(b4.z), s3 = pack1(b4.w);
            ffma2(acc[0][0], s0, ap0); ffma2(acc[1][0], s0, ap1);
            ffma2(acc[2][0], s0, ap2); ffma2(acc[3][0], s0, ap3);
            ffma2(acc[0][1], s1, ap0); ffma2(acc[1][1], s1, ap1);
            ffma2(acc[2][1], s1, ap2); ffma2(acc[3][1], s1, ap3);
            ffma2(acc[0][2], s2, ap0); ffma2(acc[1][2], s2, ap1);
            ffma2(acc[2][2], s2, ap2); ffma2(acc[3][2], s2, ap3);
            ffma2(acc[0][3], s3, ap0); ffma2(acc[1][3], s3, ap1);
            ffma2(acc[2][3], s3, ap2); ffma2(acc[3][3], s3, ap3);
        }
    }

    const int ncol = nBase + (tx << 2);
    float4 bv = *(const float4*)(bias + ncol);
#pragma unroll
    for (int i = 0; i < 4; ++i){
        float l0, h0, l1, h1, l2, h2, l3, h3;
        unpack2(acc[i][0], l0, h0);
        unpack2(acc[i][1], l1, h1);
        unpack2(acc[i][2], l2, h2);
        unpack2(acc[i][3], l3, h3);
        int m0 = mBase + (ty << 3) + (i << 1);
        float4 r0 = make_float4(l0 + bv.x, l1 + bv.y, l2 + bv.z, l3 + bv.w);
        float4 r1 = make_float4(h0 + bv.x, h1 + bv.y, h2 + bv.z, h3 + bv.w);
        *(float4*)(&g_G[dir][m0][ncol])     = r0;
        *(float4*)(&g_G[dir][m0 + 1][ncol]) = r1;
    }
}

// ---------------- Phase B: persistent bidirectional LSTM ----------------
// 128 blocks x 256 threads (8 warps). Block: one dir, 16 hidden units;
// each warp owns 2 units x 4 gates x 8 batches (batch pairs packed in f32x2).
// Gates i,f,g in smem fp32 (192 KB); gate-o rows stream from L2.
// Inactive batch pairs (t >= length) are skipped (templated on active count).
#define SMEM_PERSIST (48*1024*4 + 4*1024*8)   // 196608 + 32768 = 229376 B

template<int PACT>
__device__ __forceinline__ void lstm_step_t(
    const float* __restrict__ r0, const float* __restrict__ r1,
    const float* __restrict__ r2, const float* __restrict__ r3,
    const float* __restrict__ r4, const float* __restrict__ r5,
    const float* __restrict__ r6, const float* __restrict__ r7,
    const float2* __restrict__ hs, int lane,
    int u, int p, int half, bool act,
    float q0, float q1, float q2, float q3,
    float* hb_w, float* ho_w, float &creg, float &hreg)
{
    u64 acc[8][PACT];
#pragma unroll
    for (int r = 0; r < 8; ++r)
#pragma unroll
        for (int pp = 0; pp < PACT; ++pp) acc[r][pp] = 0ull;

    const float* const wr[8] = {r0, r1, r2, r3, r4, r5, r6, r7};

#pragma unroll 2
    for (int c = 0; c < 8; ++c){
        const int k = (c << 7) + (lane << 2);
        u64 hk[PACT][4];
#pragma unroll
        for (int pp = 0; pp < PACT; ++pp){
            ulonglong2 A = *(const ulonglong2*)&hs[(pp << 10) + k];
            ulonglong2 B = *(const ulonglong2*)&hs[(pp << 10) + k + 2];
            hk[pp][0] = A.x; hk[pp][1] = A.y; hk[pp][2] = B.x; hk[pp][3] = B.y;
        }
#pragma unroll
        for (int r = 0; r < 8; ++r){
            float4 wv = *(const float4*)(wr[r] + k);
            u64 s0 = pack1(wv.x), s1 = pack1(wv.y);
            u64 s2 = pack1(wv.z), s3 = pack1(wv.w);
#pragma unroll
            for (int pp = 0; pp < PACT; ++pp){
                ffma2(acc[r][pp], s0, hk[pp][0]);
                ffma2(acc[r][pp], s1, hk[pp][1]);
                ffma2(acc[r][pp], s2, hk[pp][2]);
                ffma2(acc[r][pp], s3, hk[pp][3]);
            }
        }
    }

    // butterfly reduce over 32 lanes
#pragma unroll
    for (int r = 0; r < 8; ++r)
#pragma unroll
        for (int pp = 0; pp < PACT; ++pp){
            u64 v = acc[r][pp];
            v = addf2(v, shfl_xor_u64(v, 16));
            v = addf2(v, shfl_xor_u64(v,  8));
            v = addf2(v, shfl_xor_u64(v,  4));
            v = addf2(v, shfl_xor_u64(v,  2));
            v = addf2(v, shfl_xor_u64(v,  1));
            acc[r][pp] = v;
        }

    if (lane < 16){
        float gs[4] = {0.f, 0.f, 0.f, 0.f};
#pragma unroll
        for (int pp = 0; pp < PACT; ++pp){
            if (pp == p){
#pragma unroll
                for (int g = 0; g < 4; ++g){
                    float lo, hi;
                    unpack2(acc[(u << 2) + g][pp], lo, hi);
                    gs[g] = half ? hi : lo;
                }
            }
        }
        if (act){
            float gi = gs[0] + q0;
            float gf = gs[1] + q1;
            float gg = gs[2] + q2;
            float go = gs[3] + q3;
            float si = fast_sigmoid(gi);
            float sf = fast_sigmoid(gf);
            float tg = fast_tanh(gg);
            float so = fast_sigmoid(go);
            creg = sf * creg + si * tg;
            hreg = so * fast_tanh(creg);
            *ho_w = hreg;
        }
        *hb_w = hreg;   // keep both buffers fresh (carry when masked)
    }
}

__global__ __launch_bounds__(256) void lstm_persist(
    const float* __restrict__ Whf, const float* __restrict__ Whb,
    const int* __restrict__ lengths)
{
    extern __shared__ char smraw[];
    float*  ws = (float*)smraw;                     // [48][1024]: gates i,f,g x 16 units
    float2* hs = (float2*)(smraw + 48*1024*4);      // [4][1024] batch-pair h

    const int blk = blockIdx.x;
    const int dir = blk >> 6;
    const int ub  = (blk & 63) << 4;
    const float* Wh = dir ? Whb : Whf;
    const int tid  = threadIdx.x;
    const int w    = tid >> 5;        // warp 0..7
    const int lane = tid & 31;
    const int n0   = ub + (w << 1);   // first of this warp's 2 units

    // preload 48 weight rows (gates i,f,g for all 16 units)
    for (int i = tid; i < 48 * 256; i += 256){
        int lr = i >> 8, q = (i & 255) << 2;
        int grow = ((lr >> 4) << 10) + ub + (lr & 15);
        float4 v = *(const float4*)(Wh + (size_t)grow * 1024 + q);
        *(float4*)&ws[lr * 1024 + q] = v;
    }

    // per-warp weight row pointers, r-order = {u0:i,f,g,o, u1:i,f,g,o}
    const float* r0 = &ws[( 0 + (n0 - ub)) * 1024];
    const float* r1 = &ws[(16 + (n0 - ub)) * 1024];
    const float* r2 = &ws[(32 + (n0 - ub)) * 1024];
    const float* r3 = Wh + (size_t)(3072 + n0) * 1024;
    const float* r4 = r0 + 1024;
    const float* r5 = r1 + 1024;
    const float* r6 = r2 + 1024;
    const float* r7 = r3 + 1024;

    const int u    = lane >> 3;       // 0/1 (meaningful for lane<16)
    const int b    = lane & 7;
    const int p    = b >> 1;
    const int half = b & 1;
    const int n    = n0 + u;
    const int lbmy = lengths[b];
    const int lb0 = lengths[0], lb2 = lengths[2];
    const int lb4 = lengths[4], lb6 = lengths[6];
    float hreg = 0.f, creg = 0.f;

    // zero t=0 read buffer
    if (lane < 16) g_hpair[0][dir][p][n][half] = 0.f;

    unsigned gen = 0;
    dir_sync(dir, gen); ++gen;

    for (int t = 0; t < 512; ++t){
        const int rbuf = t & 1, wbuf = rbuf ^ 1;
        const int pact = (t < lb0) + (t < lb2) + (t < lb4) + (t < lb6);

        // prefetch this step's G entries (latency hidden under staging+MACs)
        float q0 = 0.f, q1 = 0.f, q2 = 0.f, q3 = 0.f;
        const bool act = (lane < 16) && (t < lbmy);
        int pos = 0;
        if (act){
            pos = dir ? (lbmy - 1 - t) : t;
            const float* Gp = &g_G[dir][(b << 9) + pos][0];
            q0 = Gp[n]; q1 = Gp[1024 + n]; q2 = Gp[2048 + n]; q3 = Gp[3072 + n];
        }

        // stage active batch-pair h from L2 (written by other SMs last step)
        {
            const float4* src = (const float4*)&g_hpair[rbuf][dir][0][0][0];
            float4* dst = (float4*)hs;
            const int tot = pact << 9;
            for (int idx = tid; idx < tot; idx += 256)
                dst[idx] = __ldcg(src + idx);
        }
        __syncthreads();

        float* hb_w = &g_hpair[wbuf][dir][p][n][half];
        float* ho_w = &g_hout[dir][b][pos][n];

        switch (pact){
        case 4: lstm_step_t<4>(r0,r1,r2,r3,r4,r5,r6,r7, hs, lane, u, p, half, act,
                               q0,q1,q2,q3, hb_w, ho_w, creg, hreg); break;
        case 3: lstm_step_t<3>(r0,r1,r2,r3,r4,r5,r6,r7, hs, lane, u, p, half, act,
                               q0,q1,q2,q3, hb_w, ho_w, creg, hreg); break;
        case 2: lstm_step_t<2>(r0,r1,r2,r3,r4,r5,r6,r7, hs, lane, u, p, half, act,
                               q0,q1,q2,q3, hb_w, ho_w, creg, hreg); break;
        default: lstm_step_t<1>(r0,r1,r2,r3,r4,r5,r6,r7, hs, lane, u, p, half, act,
                               q0,q1,q2,q3, hb_w, ho_w, creg, hreg); break;
        }

        if (t < 511){ dir_sync(dir, gen); ++gen; }
    }
}

// ---------------- Phase C1: emissions ----------------
__global__ void emit_kernel(const int* __restrict__ lengths,
                            const float* __restrict__ We,
                            const float* __restrict__ be)
{
    const int t = blockIdx.x, b = blockIdx.y;
    if (t >= lengths[b]) return;
    __shared__ float h[2048];
    const int tid = threadIdx.x;
    const float* hf = &g_hout[0][b][t][0];
    const float* hb = &g_hout[1][b][t][0];
    for (int j = tid; j < 1024; j += 128){
        h[j]        = hf[j];
        h[1024 + j] = hb[j];
    }
    __syncthreads();
    const int k = tid >> 3, sub = tid & 7;
    const float* wk = We + (k << 11);
    float s = 0.f;
    for (int j = (sub << 2); j < 2048; j += 32){
        float4 wv = *(const float4*)(wk + j);
        float4 hv = *(const float4*)(&h[j]);
        s += wv.x * hv.x + wv.y * hv.y + wv.z * hv.z + wv.w * hv.w;
    }
    s += __shfl_xor_sync(0xffffffffu, s, 4);
    s += __shfl_xor_sync(0xffffffffu, s, 2);
    s += __shfl_xor_sync(0xffffffffu, s, 1);
    if (sub == 0) g_emit[b][t][k] = s + be[k];
}

// ---------------- Phase C2: CRF gold score + forward algorithm ----------------
__global__ void crf_kernel(const int* __restrict__ tags,
                           const int* __restrict__ lengths,
                           const float* __restrict__ trans,
                           float* __restrict__ out)
{
    __shared__ float T[16][16];
    const int tid = threadIdx.x;
    T[tid >> 4][tid & 15] = trans[tid];
    __syncthreads();

    const int b = tid >> 5, lane = tid & 31;
    const int lb = lengths[b];
    const int* tg = tags + (b << 9);

    float sc = 0.f;
    for (int tt = lane; tt < lb; tt += 32){
        sc += g_emit[b][tt][tg[tt]];
        if (tt >= 1) sc += T[tg[tt - 1]][tg[tt]];
    }
#pragma unroll
    for (int o = 16; o; o >>= 1) sc += __shfl_xor_sync(0xffffffffu, sc, o);

    const int j = lane & 15;
    float d = (lane < 16) ? g_emit[b][0][j] : -3e38f;
    for (int tt = 1; tt < lb; ++tt){
        float v[16];
        float mx = -3e38f;
#pragma unroll
        for (int i = 0; i < 16; ++i){
            float di = __shfl_sync(0xffffffffu, d, i);
            v[i] = di + T[i][j];
            mx = fmaxf(mx, v[i]);
        }
        float ssum = 0.f;
#pragma unroll
        for (int i = 0; i < 16; ++i) ssum += __expf(v[i] - mx);
        float nd = mx + __logf(ssum) + g_emit[b][tt][j];
        if (lane < 16) d = nd;
    }

    float mz = d;
#pragma unroll
    for (int o = 8; o; o >>= 1) mz = fmaxf(mz, __shfl_xor_sync(0xffffffffu, mz, o));
    float zs = __expf(d - mz);
#pragma unroll
    for (int o = 8; o; o >>= 1) zs += __shfl_xor_sync(0xffffffffu, zs, o);
    float logZ = mz + __logf(zs);

    if (lane == 0) out[b] = logZ - sc;
}

// ---------------- launch ----------------
extern "C" void kernel_launch(void* const* d_in, const int* in_sizes, int n_in,
                              void* d_out, int out_size)
{
    (void)in_sizes; (void)n_in; (void)out_size;
    const float* x    = (const float*)d_in[0];
    const int*   tags = (const int*)  d_in[1];
    const int*   lens = (const int*)  d_in[2];
    const float* Wihf = (const float*)d_in[3];
    const float* Whhf = (const float*)d_in[4];
    const float* bf_  = (const float*)d_in[5];
    const float* Wihb = (const float*)d_in[6];
    const float* Whhb = (const float*)d_in[7];
    const float* bb_  = (const float*)d_in[8];
    const float* We   = (const float*)d_in[9];
    const float* be   = (const float*)d_in[10];
    const float* tr   = (const float*)d_in[11];
    float* out = (float*)d_out;

    cudaFuncSetAttribute(lstm_persist,
                         cudaFuncAttributeMaxDynamicSharedMemorySize, SMEM_PERSIST);

    init_bar<<<1, 32>>>();
    proj_gemm<<<dim3(64, 32, 2), 256>>>(x, Wihf, bf_, Wihb, bb_);
    lstm_persist<<<128, 256, SMEM_PERSIST>>>(Whhf, Whhb, lens);
    emit_kernel<<<dim3(512, 8), 128>>>(lens, We, be);
    crf_kernel<<<1, 256>>>(tags, lens, tr, out);
}

// round 10
// speedup vs baseline: 1.9701x; 1.2869x over previous
#include <cuda_runtime.h>

// B=8, L=512, E=H=1024, K=16, 4H=4096
typedef unsigned long long u64;

// ---------------- scratch (static __device__; no allocations) ----------------
__device__ float g_G[2][4096][4096];          // input projections + bias
__device__ float g_hpair[2][2][4][1024][2];   // h double-buffered, batch-PAIR interleaved:
                                              // [buf][dir][p][n][half] = h[2p+half][n]
__device__ float g_hout[2][8][512][1024];     // h outputs at original positions
__device__ float g_emit[8][512][16];          // emissions
__device__ unsigned g_flag[2][64][32];        // distributed barrier flags (128B padded)

// ---------------- packed f32x2 helpers ----------------
__device__ __forceinline__ u64 pack1(float x){
    u64 r;
    asm("mov.b64 %0, {%1, %1};" : "=l"(r) : "r"(__float_as_uint(x)));
    return r;
}
__device__ __forceinline__ void unpack2(u64 v, float &x, float &y){
    unsigned a, b;
    asm("mov.b64 {%0, %1}, %2;" : "=r"(a), "=r"(b) : "l"(v));
    x = __uint_as_float(a); y = __uint_as_float(b);
}
__device__ __forceinline__ void ffma2(u64 &acc, u64 a, u64 b){
    asm("fma.rn.f32x2 %0, %1, %2, %0;" : "+l"(acc) : "l"(a), "l"(b));
}
__device__ __forceinline__ u64 addf2(u64 a, u64 b){
    u64 r;
    asm("add.rn.f32x2 %0, %1, %2;" : "=l"(r) : "l"(a), "l"(b));
    return r;
}
__device__ __forceinline__ u64 shfl_xor_u64(u64 v, int m){
    unsigned lo = (unsigned)(v & 0xffffffffull);
    unsigned hi = (unsigned)(v >> 32);
    lo = __shfl_xor_sync(0xffffffffu, lo, m);
    hi = __shfl_xor_sync(0xffffffffu, hi, m);
    return ((u64)hi << 32) | (u64)lo;
}
__device__ __forceinline__ u64 shfl_idx_u64(u64 v, int src){
    unsigned lo = (unsigned)(v & 0xffffffffull);
    unsigned hi = (unsigned)(v >> 32);
    lo = __shfl_sync(0xffffffffu, lo, src);
    hi = __shfl_sync(0xffffffffu, hi, src);
    return ((u64)hi << 32) | (u64)lo;
}
__device__ __forceinline__ float fast_sigmoid(float x){
    return 1.f / (1.f + __expf(-x));
}
__device__ __forceinline__ float fast_tanh(float x){
    return 1.f - 2.f / (__expf(2.f * x) + 1.f);   // stable at both infinities
}

// ---------------- distributed per-direction grid barrier (64 blocks) ----------------
// Arrive: one release-store to my own padded flag. Wait: threads 0..63 each
// spin-acquire on one flag. No atomic serialization, one L2 hop to detect.
__device__ __forceinline__ void dir_sync(int dir, int myblk, unsigned target){
    __syncthreads();   // block's global writes happen-before the release below
    if (threadIdx.x == 0){
        asm volatile("st.release.gpu.global.u32 [%0], %1;"
                     :: "l"(&g_flag[dir][myblk][0]), "r"(target) : "memory");
    }
    if (threadIdx.x < 64){
        unsigned v;
        do {
            asm volatile("ld.acquire.gpu.global.u32 %0, [%1];"
                         : "=r"(v) : "l"(&g_flag[dir][threadIdx.x][0]) : "memory");
        } while (v < target);
    }
    __syncthreads();
}

__global__ void init_bar(){
    int i = threadIdx.x;
    unsigned* f = &g_flag[0][0][0];
    for (int idx = i; idx < 2 * 64 * 32; idx += 256) f[idx] = 0u;
}

// ---------------- Phase A: G = X @ W_ih^T + b (both directions) ----------------
// Block tile 128(M) x 64(N), K-tile 16, 256 threads. M-row-pair packed accs.
// Register double buffering: prefetch kt+1's global loads before computing kt.
__global__ __launch_bounds__(256) void proj_gemm(
    const float* __restrict__ x,
    const float* __restrict__ Wf, const float* __restrict__ bf,
    const float* __restrict__ Wb, const float* __restrict__ bb)
{
    __shared__ float As[16][136];   // [k][row 0..127]
    __shared__ float Bs[16][72];    // [k][col 0..63]
    const int dir = blockIdx.z;
    const float* W    = dir ? Wb : Wf;
    const float* bias = dir ? bb : bf;
    const int tid = threadIdx.x;
    const int mBase = blockIdx.y << 7;
    const int nBase = blockIdx.x << 6;
    const int tx = tid & 15;
    const int ty = tid >> 4;

    const int ar = tid >> 1;            // 0..127
    const int ak = (tid & 1) << 3;      // 0 or 8
    const int br = tid >> 2;            // 0..63
    const int bk = (tid & 3) << 2;      // 0,4,8,12

    const float* xp = x + (size_t)(mBase + ar) * 1024 + ak;
    const float* wp = W + (size_t)(nBase + br) * 1024 + bk;

    u64 acc[4][4];
#pragma unroll
    for (int i = 0; i < 4; ++i)
#pragma unroll
        for (int j = 0; j < 4; ++j) acc[i][j] = 0ull;

    float4 a0 = *(const float4*)(xp);
    float4 a1 = *(const float4*)(xp + 4);
    float4 bv = *(const float4*)(wp);

    for (int kt = 0; kt < 64; ++kt){
        __syncthreads();
        As[ak + 0][ar] = a0.x; As[ak + 1][ar] = a0.y;
        As[ak + 2][ar] = a0.z; As[ak + 3][ar] = a0.w;
        As[ak + 4][ar] = a1.x; As[ak + 5][ar] = a1.y;
        As[ak + 6][ar] = a1.z; As[ak + 7][ar] = a1.w;
        Bs[bk + 0][br] = bv.x; Bs[bk + 1][br] = bv.y;
        Bs[bk + 2][br] = bv.z; Bs[bk + 3][br] = bv.w;
        __syncthreads();
        if (kt < 63){
            a0 = *(const float4*)(xp + (kt + 1) * 16);
            a1 = *(const float4*)(xp + (kt + 1) * 16 + 4);
            bv = *(const float4*)(wp + (kt + 1) * 16);
        }
#pragma unroll
        for (int kk = 0; kk < 16; ++kk){
            ulonglong2 A0 = *(const ulonglong2*)&As[kk][ty << 3];
            ulonglong2 A1 = *(const ulonglong2*)&As[kk][(ty << 3) + 4];
            u64 ap0 = A0.x, ap1 = A0.y, ap2 = A1.x, ap3 = A1.y;
            float4 b4 = *(const float4*)&Bs[kk][tx << 2];
            u64 s0 = pack1(b4.x), s1 = pack1(b4.y);
            u64 s2 = pack1(b4.z), s3 = pack1(b4.w);
            ffma2(acc[0][0], s0, ap0); ffma2(acc[1][0], s0, ap1);
            ffma2(acc[2][0], s0, ap2); ffma2(acc[3][0], s0, ap3);
            ffma2(acc[0][1], s1, ap0); ffma2(acc[1][1], s1, ap1);
            ffma2(acc[2][1], s1, ap2); ffma2(acc[3][1], s1, ap3);
            ffma2(acc[0][2], s2, ap0); ffma2(acc[1][2], s2, ap1);
            ffma2(acc[2][2], s2, ap2); ffma2(acc[3][2], s2, ap3);
            ffma2(acc[0][3], s3, ap0); ffma2(acc[1][3], s3, ap1);
            ffma2(acc[2][3], s3, ap2); ffma2(acc[3][3], s3, ap3);
        }
    }

    const int ncol = nBase + (tx << 2);
    float4 bb4 = *(const float4*)(bias + ncol);
#pragma unroll
    for (int i = 0; i < 4; ++i){
        float l0, h0, l1, h1, l2, h2, l3, h3;
        unpack2(acc[i][0], l0, h0);
        unpack2(acc[i][1], l1, h1);
        unpack2(acc[i][2], l2, h2);
        unpack2(acc[i][3], l3, h3);
        int m0 = mBase + (ty << 3) + (i << 1);
        float4 r0 = make_float4(l0 + bb4.x, l1 + bb4.y, l2 + bb4.z, l3 + bb4.w);
        float4 r1 = make_float4(h0 + bb4.x, h1 + bb4.y, h2 + bb4.z, h3 + bb4.w);
        *(float4*)(&g_G[dir][m0][ncol])     = r0;
        *(float4*)(&g_G[dir][m0 + 1][ncol]) = r1;
    }
}

// ---------------- Phase B: persistent bidirectional LSTM ----------------
#define SMEM_PERSIST (48*1024*4 + 4*1024*8)   // 229376 B

template<int PACT>
__device__ __forceinline__ void lstm_step_t(
    const float* __restrict__ r0, const float* __restrict__ r1,
    const float* __restrict__ r2, const float* __restrict__ r3,
    const float* __restrict__ r4, const float* __restrict__ r5,
    const float* __restrict__ r6, const float* __restrict__ r7,
    const float2* __restrict__ hs, int lane,
    int u, int p, int half, bool act,
    float q0, float q1, float q2, float q3,
    float* hb_w, float* ho_w, float &creg, float &hreg)
{
    u64 acc[8][PACT];
#pragma unroll
    for (int r = 0; r < 8; ++r)
#pragma unroll
        for (int pp = 0; pp < PACT; ++pp) acc[r][pp] = 0ull;

    const float* const wr[8] = {r0, r1, r2, r3, r4, r5, r6, r7};

#pragma unroll 2
    for (int c = 0; c < 8; ++c){
        const int k = (c << 7) + (lane << 2);
        u64 hk[PACT][4];
#pragma unroll
        for (int pp = 0; pp < PACT; ++pp){
            ulonglong2 A = *(const ulonglong2*)&hs[(pp << 10) + k];
            ulonglong2 B = *(const ulonglong2*)&hs[(pp << 10) + k + 2];
            hk[pp][0] = A.x; hk[pp][1] = A.y; hk[pp][2] = B.x; hk[pp][3] = B.y;
        }
#pragma unroll
        for (int r = 0; r < 8; ++r){
            float4 wv = *(const float4*)(wr[r] + k);
            u64 s0 = pack1(wv.x), s1 = pack1(wv.y);
            u64 s2 = pack1(wv.z), s3 = pack1(wv.w);
#pragma unroll
            for (int pp = 0; pp < PACT; ++pp){
                ffma2(acc[r][pp], s0, hk[pp][0]);
                ffma2(acc[r][pp], s1, hk[pp][1]);
                ffma2(acc[r][pp], s2, hk[pp][2]);
                ffma2(acc[r][pp], s3, hk[pp][3]);
            }
        }
    }

    // ---- reduce-scatter over 32 lanes: 31 shfl_u64 total ----
    // value index a = pp*8 + r; after 5 stages lane L holds sum of A[L].
    u64 A[32];
#pragma unroll
    for (int pp = 0; pp < 4; ++pp)
#pragma unroll
        for (int r = 0; r < 8; ++r)
            A[(pp << 3) + r] = (pp < PACT) ? acc[r][pp] : 0ull;

    u64 B16[16];
#pragma unroll
    for (int i = 0; i < 16; ++i){
        u64 send = (lane & 16) ? A[i] : A[i + 16];
        u64 recv = shfl_xor_u64(send, 16);
        u64 keep = (lane & 16) ? A[i + 16] : A[i];
        B16[i] = addf2(keep, recv);
    }
    u64 B8[8];
#pragma unroll
    for (int i = 0; i < 8; ++i){
        u64 send = (lane & 8) ? B16[i] : B16[i + 8];
        u64 recv = shfl_xor_u64(send, 8);
        u64 keep = (lane & 8) ? B16[i + 8] : B16[i];
        B8[i] = addf2(keep, recv);
    }
    u64 B4[4];
#pragma unroll
    for (int i = 0; i < 4; ++i){
        u64 send = (lane & 4) ? B8[i] : B8[i + 4];
        u64 recv = shfl_xor_u64(send, 4);
        u64 keep = (lane & 4) ? B8[i + 4] : B8[i];
        B4[i] = addf2(keep, recv);
    }
    u64 B2[2];
#pragma unroll
    for (int i = 0; i < 2; ++i){
        u64 send = (lane & 2) ? B4[i] : B4[i + 2];
        u64 recv = shfl_xor_u64(send, 2);
        u64 keep = (lane & 2) ? B4[i + 2] : B4[i];
        B2[i] = addf2(keep, recv);
    }
    u64 red;
    {
        u64 send = (lane & 1) ? B2[0] : B2[1];
        u64 recv = shfl_xor_u64(send, 1);
        u64 keep = (lane & 1) ? B2[1] : B2[0];
        red = addf2(keep, recv);
    }

    // gather this lane's 4 gate values (a = p*8 + u*4 + g)
    const int basei = ((p << 3) + (u << 2)) & 31;
    u64 G0 = shfl_idx_u64(red, basei);
    u64 G1 = shfl_idx_u64(red, basei + 1);
    u64 G2 = shfl_idx_u64(red, basei + 2);
    u64 G3 = shfl_idx_u64(red, basei + 3);

    if (lane < 16){
        float lo, hi, gs0, gs1, gs2, gs3;
        unpack2(G0, lo, hi); gs0 = half ? hi : lo;
        unpack2(G1, lo, hi); gs1 = half ? hi : lo;
        unpack2(G2, lo, hi); gs2 = half ? hi : lo;
        unpack2(G3, lo, hi); gs3 = half ? hi : lo;
        if (act){
            float gi = gs0 + q0;
            float gf = gs1 + q1;
            float gg = gs2 + q2;
            float go = gs3 + q3;
            float si = fast_sigmoid(gi);
            float sf = fast_sigmoid(gf);
            float tg = fast_tanh(gg);
            float so = fast_sigmoid(go);
            creg = sf * creg + si * tg;
            hreg = so * fast_tanh(creg);
            *ho_w = hreg;
        }
        *hb_w = hreg;   // keep both buffers fresh (carry when masked)
    }
}

__global__ __launch_bounds__(256) void lstm_persist(
    const float* __restrict__ Whf, const float* __restrict__ Whb,
    const int* __restrict__ lengths)
{
    extern __shared__ char smraw[];
    float*  ws = (float*)smraw;                     // [48][1024]: gates i,f,g x 16 units
    float2* hs = (float2*)(smraw + 48*1024*4);      // [4][1024] batch-pair h

    const int blk = blockIdx.x;
    const int dir = blk >> 6;
    const int myblk = blk & 63;
    const int ub  = myblk << 4;
    const float* Wh = dir ? Whb : Whf;
    const int tid  = threadIdx.x;
    const int w    = tid >> 5;        // warp 0..7
    const int lane = tid & 31;
    const int n0   = ub + (w << 1);

    // preload 48 weight rows (gates i,f,g for all 16 units)
    for (int i = tid; i < 48 * 256; i += 256){
        int lr = i >> 8, q = (i & 255) << 2;
        int grow = ((lr >> 4) << 10) + ub + (lr & 15);
        float4 v = *(const float4*)(Wh + (size_t)grow * 1024 + q);
        *(float4*)&ws[lr * 1024 + q] = v;
    }

    const float* r0 = &ws[( 0 + (n0 - ub)) * 1024];
    const float* r1 = &ws[(16 + (n0 - ub)) * 1024];
    const float* r2 = &ws[(32 + (n0 - ub)) * 1024];
    const float* r3 = Wh + (size_t)(3072 + n0) * 1024;
    const float* r4 = r0 + 1024;
    const float* r5 = r1 + 1024;
    const float* r6 = r2 + 1024;
    const float* r7 = r3 + 1024;

    const int u    = lane >> 3;
    const int b    = lane & 7;
    const int p    = b >> 1;
    const int half = b & 1;
    const int n    = n0 + u;
    const int lbmy = lengths[b];
    const int lb0 = lengths[0], lb2 = lengths[2];
    const int lb4 = lengths[4], lb6 = lengths[6];
    float hreg = 0.f, creg = 0.f;

    if (lane < 16) g_hpair[0][dir][p][n][half] = 0.f;

    dir_sync(dir, myblk, 1u);

    for (int t = 0; t < 512; ++t){
        const int rbuf = t & 1, wbuf = rbuf ^ 1;
        const int pact = (t < lb0) + (t < lb2) + (t < lb4) + (t < lb6);

        float q0 = 0.f, q1 = 0.f, q2 = 0.f, q3 = 0.f;
        const bool act = (lane < 16) && (t < lbmy);
        int pos = 0;
        if (act){
            pos = dir ? (lbmy - 1 - t) : t;
            const float* Gp = &g_G[dir][(b << 9) + pos][0];
            q0 = Gp[n]; q1 = Gp[1024 + n]; q2 = Gp[2048 + n]; q3 = Gp[3072 + n];
        }

        {
            const float4* src = (const float4*)&g_hpair[rbuf][dir][0][0][0];
            float4* dst = (float4*)hs;
            const int tot = pact << 9;
            for (int idx = tid; idx < tot; idx += 256)
                dst[idx] = __ldcg(src + idx);
        }
        __syncthreads();

        float* hb_w = &g_hpair[wbuf][dir][p][n][half];
        float* ho_w = &g_hout[dir][b][pos][n];

        switch (pact){
        case 4: lstm_step_t<4>(r0,r1,r2,r3,r4,r5,r6,r7, hs, lane, u, p, half, act,
                               q0,q1,q2,q3, hb_w, ho_w, creg, hreg); break;
        case 3: lstm_step_t<3>(r0,r1,r2,r3,r4,r5,r6,r7, hs, lane, u, p, half, act,
                               q0,q1,q2,q3, hb_w, ho_w, creg, hreg); break;
        case 2: lstm_step_t<2>(r0,r1,r2,r3,r4,r5,r6,r7, hs, lane, u, p, half, act,
                               q0,q1,q2,q3, hb_w, ho_w, creg, hreg); break;
        default: lstm_step_t<1>(r0,r1,r2,r3,r4,r5,r6,r7, hs, lane, u, p, half, act,
                               q0,q1,q2,q3, hb_w, ho_w, creg, hreg); break;
        }

        if (t < 511) dir_sync(dir, myblk, (unsigned)(t + 2));
    }
}

// ---------------- Phase C1: emissions ----------------
__global__ void emit_kernel(const int* __restrict__ lengths,
                            const float* __restrict__ We,
                            const float* __restrict__ be)
{
    const int t = blockIdx.x, b = blockIdx.y;
    if (t >= lengths[b]) return;
    __shared__ float h[2048];
    const int tid = threadIdx.x;
    const float* hf = &g_hout[0][b][t][0];
    const float* hb = &g_hout[1][b][t][0];
    for (int j = tid; j < 1024; j += 128){
        h[j]        = hf[j];
        h[1024 + j] = hb[j];
    }
    __syncthreads();
    const int k = tid >> 3, sub = tid & 7;
    const float* wk = We + (k << 11);
    float s = 0.f;
    for (int j = (sub << 2); j < 2048; j += 32){
        float4 wv = *(const float4*)(wk + j);
        float4 hv = *(const float4*)(&h[j]);
        s += wv.x * hv.x + wv.y * hv.y + wv.z * hv.z + wv.w * hv.w;
    }
    s += __shfl_xor_sync(0xffffffffu, s, 4);
    s += __shfl_xor_sync(0xffffffffu, s, 2);
    s += __shfl_xor_sync(0xffffffffu, s, 1);
    if (sub == 0) g_emit[b][t][k] = s + be[k];
}

// ---------------- Phase C2: CRF gold score + forward algorithm ----------------
__global__ void crf_kernel(const int* __restrict__ tags,
                           const int* __restrict__ lengths,
                           const float* __restrict__ trans,
                           float* __restrict__ out)
{
    __shared__ float T[16][16];
    const int tid = threadIdx.x;
    T[tid >> 4][tid & 15] = trans[tid];
    __syncthreads();

    const int b = tid >> 5, lane = tid & 31;
    const int lb = lengths[b];
    const int* tg = tags + (b << 9);

    float sc = 0.f;
    for (int tt = lane; tt < lb; tt += 32){
        sc += g_emit[b][tt][tg[tt]];
        if (tt >= 1) sc += T[tg[tt - 1]][tg[tt]];
    }
#pragma unroll
    for (int o = 16; o; o >>= 1) sc += __shfl_xor_sync(0xffffffffu, sc, o);

    const int j = lane & 15;
    float d = (lane < 16) ? g_emit[b][0][j] : -3e38f;
    for (int tt = 1; tt < lb; ++tt){
        float v[16];
        float mx = -3e38f;
#pragma unroll
        for (int i = 0; i < 16; ++i){
            float di = __shfl_sync(0xffffffffu, d, i);
            v[i] = di + T[i][j];
            mx = fmaxf(mx, v[i]);
        }
        float ssum = 0.f;
#pragma unroll
        for (int i = 0; i < 16; ++i) ssum += __expf(v[i] - mx);
        float nd = mx + __logf(ssum) + g_emit[b][tt][j];
        if (lane < 16) d = nd;
    }

    float mz = d;
#pragma unroll
    for (int o = 8; o; o >>= 1) mz = fmaxf(mz, __shfl_xor_sync(0xffffffffu, mz, o));
    float zs = __expf(d - mz);
#pragma unroll
    for (int o = 8; o; o >>= 1) zs += __shfl_xor_sync(0xffffffffu, zs, o);
    float logZ = mz + __logf(zs);

    if (lane == 0) out[b] = logZ - sc;
}

// ---------------- launch ----------------
extern "C" void kernel_launch(void* const* d_in, const int* in_sizes, int n_in,
                              void* d_out, int out_size)
{
    (void)in_sizes; (void)n_in; (void)out_size;
    const float* x    = (const float*)d_in[0];
    const int*   tags = (const int*)  d_in[1];
    const int*   lens = (const int*)  d_in[2];
    const float* Wihf = (const float*)d_in[3];
    const float* Whhf = (const float*)d_in[4];
    const float* bf_  = (const float*)d_in[5];
    const float* Wihb = (const float*)d_in[6];
    const float* Whhb = (const float*)d_in[7];
    const float* bb_  = (const float*)d_in[8];
    const float* We   = (const float*)d_in[9];
    const float* be   = (const float*)d_in[10];
    const float* tr   = (const float*)d_in[11];
    float* out = (float*)d_out;

    cudaFuncSetAttribute(lstm_persist,
                         cudaFuncAttributeMaxDynamicSharedMemorySize, SMEM_PERSIST);

    init_bar<<<1, 256>>>();
    proj_gemm<<<dim3(64, 32, 2), 256>>>(x, Wihf, bf_, Wihb, bb_);
    lstm_persist<<<128, 256, SMEM_PERSIST>>>(Whhf, Whhb, lens);
    emit_kernel<<<dim3(512, 8), 128>>>(lens, We, be);
    crf_kernel<<<1, 256>>>(tags, lens, tr, out);
}

// round 11
// speedup vs baseline: 2.3008x; 1.1679x over previous
#include <cuda_runtime.h>

// B=8, L=512, E=H=1024, K=16, 4H=4096
typedef unsigned long long u64;

// ---------------- scratch (static __device__; no allocations) ----------------
__device__ float g_G[2][4096][4096];          // input projections + bias
__device__ float g_hpair[2][2][4][1024][2];   // h double-buffered, batch-PAIR interleaved
__device__ float g_hout[2][8][512][1024];     // h outputs at original positions
__device__ float g_emit[8][512][16];          // emissions
__device__ unsigned g_flag[2][64][32];        // distributed barrier flags (128B padded)

// ---------------- packed f32x2 helpers ----------------
__device__ __forceinline__ u64 pack1(float x){
    u64 r;
    asm("mov.b64 %0, {%1, %1};" : "=l"(r) : "r"(__float_as_uint(x)));
    return r;
}
__device__ __forceinline__ void unpack2(u64 v, float &x, float &y){
    unsigned a, b;
    asm("mov.b64 {%0, %1}, %2;" : "=r"(a), "=r"(b) : "l"(v));
    x = __uint_as_float(a); y = __uint_as_float(b);
}
__device__ __forceinline__ void ffma2(u64 &acc, u64 a, u64 b){
    asm("fma.rn.f32x2 %0, %1, %2, %0;" : "+l"(acc) : "l"(a), "l"(b));
}
__device__ __forceinline__ u64 addf2(u64 a, u64 b){
    u64 r;
    asm("add.rn.f32x2 %0, %1, %2;" : "=l"(r) : "l"(a), "l"(b));
    return r;
}
__device__ __forceinline__ u64 shfl_xor_u64(u64 v, int m){
    unsigned lo = (unsigned)(v & 0xffffffffull);
    unsigned hi = (unsigned)(v >> 32);
    lo = __shfl_xor_sync(0xffffffffu, lo, m);
    hi = __shfl_xor_sync(0xffffffffu, hi, m);
    return ((u64)hi << 32) | (u64)lo;
}
__device__ __forceinline__ u64 shfl_idx_u64(u64 v, int src){
    unsigned lo = (unsigned)(v & 0xffffffffull);
    unsigned hi = (unsigned)(v >> 32);
    lo = __shfl_sync(0xffffffffu, lo, src);
    hi = __shfl_sync(0xffffffffu, hi, src);
    return ((u64)hi << 32) | (u64)lo;
}
__device__ __forceinline__ float fast_sigmoid(float x){
    return 1.f / (1.f + __expf(-x));
}
__device__ __forceinline__ float fast_tanh(float x){
    return 1.f - 2.f / (__expf(2.f * x) + 1.f);   // stable at both infinities
}

// ---------------- distributed per-direction grid barrier (64 blocks) ----------------
__device__ __forceinline__ void dir_sync(int dir, int myblk, unsigned target){
    __syncthreads();
    if (threadIdx.x == 0){
        asm volatile("st.release.gpu.global.u32 [%0], %1;"
                     :: "l"(&g_flag[dir][myblk][0]), "r"(target) : "memory");
    }
    if (threadIdx.x < 64){
        unsigned v;
        do {
            asm volatile("ld.acquire.gpu.global.u32 %0, [%1];"
                         : "=r"(v) : "l"(&g_flag[dir][threadIdx.x][0]) : "memory");
        } while (v < target);
    }
    __syncthreads();
}

__global__ void init_bar(){
    int i = threadIdx.x;
    unsigned* f = &g_flag[0][0][0];
    for (int idx = i; idx < 2 * 64 * 32; idx += 256) f[idx] = 0u;
}

// ---------------- Phase A: G = X @ W_ih^T + b via tf32 tensor cores ----------------
// Block tile 128(M) x 128(N), K-tile 16, 256 threads = 8 warps as 2(m) x 4(n).
// Warp tile 64 x 32 = 4x4 grid of m16n8k8 tf32 mma (fp32 accumulate).
// Smem [row][k] with stride 20 -> fragment LDS hits 32 distinct banks.
__device__ __forceinline__ void mma_tf32(
    float &d0, float &d1, float &d2, float &d3,
    unsigned a0, unsigned a1, unsigned a2, unsigned a3,
    unsigned b0, unsigned b1)
{
    asm volatile(
        "mma.sync.aligned.m16n8k8.row.col.f32.tf32.tf32.f32 "
        "{%0,%1,%2,%3}, {%4,%5,%6,%7}, {%8,%9}, {%0,%1,%2,%3};"
        : "+f"(d0), "+f"(d1), "+f"(d2), "+f"(d3)
        : "r"(a0), "r"(a1), "r"(a2), "r"(a3), "r"(b0), "r"(b1));
}

__global__ __launch_bounds__(256) void proj_gemm_tc(
    const float* __restrict__ x,
    const float* __restrict__ Wf, const float* __restrict__ bf,
    const float* __restrict__ Wb, const float* __restrict__ bb)
{
    __shared__ float As[128 * 20];   // [m][k], k stride 20 (16 used + 4 pad)
    __shared__ float Bs[128 * 20];   // [n][k]
    const int dir = blockIdx.z;
    const float* W    = dir ? Wb : Wf;
    const float* bias = dir ? bb : bf;
    const int tid = threadIdx.x;
    const int mBase = blockIdx.y << 7;
    const int nBase = blockIdx.x << 7;
    const int warp = tid >> 5, lane = tid & 31;
    const int wm = warp & 1;         // 0..1
    const int wn = warp >> 1;        // 0..3
    const int lr = lane >> 2;        // 0..7
    const int lc = lane & 3;         // 0..3

    const int grow = tid >> 1;           // 0..127
    const int gk   = (tid & 1) << 3;     // 0 or 8

    const float* xp = x + (size_t)(mBase + grow) * 1024 + gk;
    const float* wp = W + (size_t)(nBase + grow) * 1024 + gk;

    float acc[4][4][4];   // [mt][nt][c]
#pragma unroll
    for (int i = 0; i < 4; ++i)
#pragma unroll
        for (int j = 0; j < 4; ++j)
#pragma unroll
            for (int c = 0; c < 4; ++c) acc[i][j][c] = 0.f;

    float4 ax0 = *(const float4*)(xp);
    float4 ax1 = *(const float4*)(xp + 4);
    float4 bx0 = *(const float4*)(wp);
    float4 bx1 = *(const float4*)(wp + 4);

    for (int kt = 0; kt < 64; ++kt){
        __syncthreads();
        *(float4*)&As[grow * 20 + gk]     = ax0;
        *(float4*)&As[grow * 20 + gk + 4] = ax1;
        *(float4*)&Bs[grow * 20 + gk]     = bx0;
        *(float4*)&Bs[grow * 20 + gk + 4] = bx1;
        __syncthreads();
        if (kt < 63){
            ax0 = *(const float4*)(xp + (kt + 1) * 16);
            ax1 = *(const float4*)(xp + (kt + 1) * 16 + 4);
            bx0 = *(const float4*)(wp + (kt + 1) * 16);
            bx1 = *(const float4*)(wp + (kt + 1) * 16 + 4);
        }
#pragma unroll
        for (int k8 = 0; k8 < 2; ++k8){
            const int kb = (k8 << 3) + lc;
            unsigned af[4][4];
#pragma unroll
            for (int mt = 0; mt < 4; ++mt){
                const int m0 = (wm << 6) + (mt << 4);
                af[mt][0] = __float_as_uint(As[(m0 + lr)     * 20 + kb]);
                af[mt][1] = __float_as_uint(As[(m0 + lr + 8) * 20 + kb]);
                af[mt][2] = __float_as_uint(As[(m0 + lr)     * 20 + kb + 4]);
                af[mt][3] = __float_as_uint(As[(m0 + lr + 8) * 20 + kb + 4]);
            }
            unsigned bfr[4][2];
#pragma unroll
            for (int nt = 0; nt < 4; ++nt){
                const int n0 = (wn << 5) + (nt << 3);
                bfr[nt][0] = __float_as_uint(Bs[(n0 + lr) * 20 + kb]);
                bfr[nt][1] = __float_as_uint(Bs[(n0 + lr) * 20 + kb + 4]);
            }
#pragma unroll
            for (int mt = 0; mt < 4; ++mt)
#pragma unroll
                for (int nt = 0; nt < 4; ++nt)
                    mma_tf32(acc[mt][nt][0], acc[mt][nt][1],
                             acc[mt][nt][2], acc[mt][nt][3],
                             af[mt][0], af[mt][1], af[mt][2], af[mt][3],
                             bfr[nt][0], bfr[nt][1]);
        }
    }

    // epilogue: D(16x8) c0/c1 at (lr, 2lc), c2/c3 at (lr+8, 2lc); add bias
#pragma unroll
    for (int nt = 0; nt < 4; ++nt){
        const int gcol = nBase + (wn << 5) + (nt << 3) + (lc << 1);
        float2 bv = *(const float2*)(bias + gcol);
#pragma unroll
        for (int mt = 0; mt < 4; ++mt){
            const int grow0 = mBase + (wm << 6) + (mt << 4) + lr;
            float2 r0 = make_float2(acc[mt][nt][0] + bv.x, acc[mt][nt][1] + bv.y);
            float2 r1 = make_float2(acc[mt][nt][2] + bv.x, acc[mt][nt][3] + bv.y);
            *(float2*)(&g_G[dir][grow0][gcol])     = r0;
            *(float2*)(&g_G[dir][grow0 + 8][gcol]) = r1;
        }
    }
}

// ---------------- Phase B: persistent bidirectional LSTM ----------------
#define SMEM_PERSIST (48*1024*4 + 4*1024*8)   // 229376 B

template<int PACT>
__device__ __forceinline__ void lstm_step_t(
    const float* __restrict__ r0, const float* __restrict__ r1,
    const float* __restrict__ r2, const float* __restrict__ r3,
    const float* __restrict__ r4, const float* __restrict__ r5,
    const float* __restrict__ r6, const float* __restrict__ r7,
    const float2* __restrict__ hs, int lane,
    int u, int p, int half, bool act,
    float q0, float q1, float q2, float q3,
    float* hb_w, float* ho_w, float &creg, float &hreg)
{
    u64 acc[8][PACT];
#pragma unroll
    for (int r = 0; r < 8; ++r)
#pragma unroll
        for (int pp = 0; pp < PACT; ++pp) acc[r][pp] = 0ull;

    const float* const wr[8] = {r0, r1, r2, r3, r4, r5, r6, r7};

#pragma unroll 2
    for (int c = 0; c < 8; ++c){
        const int k = (c << 7) + (lane << 2);
        u64 hk[PACT][4];
#pragma unroll
        for (int pp = 0; pp < PACT; ++pp){
            ulonglong2 A = *(const ulonglong2*)&hs[(pp << 10) + k];
            ulonglong2 B = *(const ulonglong2*)&hs[(pp << 10) + k + 2];
            hk[pp][0] = A.x; hk[pp][1] = A.y; hk[pp][2] = B.x; hk[pp][3] = B.y;
        }
#pragma unroll
        for (int r = 0; r < 8; ++r){
            float4 wv = *(const float4*)(wr[r] + k);
            u64 s0 = pack1(wv.x), s1 = pack1(wv.y);
            u64 s2 = pack1(wv.z), s3 = pack1(wv.w);
#pragma unroll
            for (int pp = 0; pp < PACT; ++pp){
                ffma2(acc[r][pp], s0, hk[pp][0]);
                ffma2(acc[r][pp], s1, hk[pp][1]);
                ffma2(acc[r][pp], s2, hk[pp][2]);
                ffma2(acc[r][pp], s3, hk[pp][3]);
            }
        }
    }

    // ---- reduce-scatter over 32 lanes: 31 shfl_u64 total ----
    u64 A[32];
#pragma unroll
    for (int pp = 0; pp < 4; ++pp)
#pragma unroll
        for (int r = 0; r < 8; ++r)
            A[(pp << 3) + r] = (pp < PACT) ? acc[r][pp] : 0ull;

    u64 B16[16];
#pragma unroll
    for (int i = 0; i < 16; ++i){
        u64 send = (lane & 16) ? A[i] : A[i + 16];
        u64 recv = shfl_xor_u64(send, 16);
        u64 keep = (lane & 16) ? A[i + 16] : A[i];
        B16[i] = addf2(keep, recv);
    }
    u64 B8[8];
#pragma unroll
    for (int i = 0; i < 8; ++i){
        u64 send = (lane & 8) ? B16[i] : B16[i + 8];
        u64 recv = shfl_xor_u64(send, 8);
        u64 keep = (lane & 8) ? B16[i + 8] : B16[i];
        B8[i] = addf2(keep, recv);
    }
    u64 B4[4];
#pragma unroll
    for (int i = 0; i < 4; ++i){
        u64 send = (lane & 4) ? B8[i] : B8[i + 4];
        u64 recv = shfl_xor_u64(send, 4);
        u64 keep = (lane & 4) ? B8[i + 4] : B8[i];
        B4[i] = addf2(keep, recv);
    }
    u64 B2[2];
#pragma unroll
    for (int i = 0; i < 2; ++i){
        u64 send = (lane & 2) ? B4[i] : B4[i + 2];
        u64 recv = shfl_xor_u64(send, 2);
        u64 keep = (lane & 2) ? B4[i + 2] : B4[i];
        B2[i] = addf2(keep, recv);
    }
    u64 red;
    {
        u64 send = (lane & 1) ? B2[0] : B2[1];
        u64 recv = shfl_xor_u64(send, 1);
        u64 keep = (lane & 1) ? B2[1] : B2[0];
        red = addf2(keep, recv);
    }

    const int basei = ((p << 3) + (u << 2)) & 31;
    u64 G0 = shfl_idx_u64(red, basei);
    u64 G1 = shfl_idx_u64(red, basei + 1);
    u64 G2 = shfl_idx_u64(red, basei + 2);
    u64 G3 = shfl_idx_u64(red, basei + 3);

    if (lane < 16){
        float lo, hi, gs0, gs1, gs2, gs3;
        unpack2(G0, lo, hi); gs0 = half ? hi : lo;
        unpack2(G1, lo, hi); gs1 = half ? hi : lo;
        unpack2(G2, lo, hi); gs2 = half ? hi : lo;
        unpack2(G3, lo, hi); gs3 = half ? hi : lo;
        if (act){
            float gi = gs0 + q0;
            float gf = gs1 + q1;
            float gg = gs2 + q2;
            float go = gs3 + q3;
            float si = fast_sigmoid(gi);
            float sf = fast_sigmoid(gf);
            float tg = fast_tanh(gg);
            float so = fast_sigmoid(go);
            creg = sf * creg + si * tg;
            hreg = so * fast_tanh(creg);
            *ho_w = hreg;
        }
        *hb_w = hreg;
    }
}

__global__ __launch_bounds__(256) void lstm_persist(
    const float* __restrict__ Whf, const float* __restrict__ Whb,
    const int* __restrict__ lengths)
{
    extern __shared__ char smraw[];
    float*  ws = (float*)smraw;                     // [48][1024]
    float2* hs = (float2*)(smraw + 48*1024*4);      // [4][1024]

    const int blk = blockIdx.x;
    const int dir = blk >> 6;
    const int myblk = blk & 63;
    const int ub  = myblk << 4;
    const float* Wh = dir ? Whb : Whf;
    const int tid  = threadIdx.x;
    const int w    = tid >> 5;
    const int lane = tid & 31;
    const int n0   = ub + (w << 1);

    for (int i = tid; i < 48 * 256; i += 256){
        int lr = i >> 8, q = (i & 255) << 2;
        int grow = ((lr >> 4) << 10) + ub + (lr & 15);
        float4 v = *(const float4*)(Wh + (size_t)grow * 1024 + q);
        *(float4*)&ws[lr * 1024 + q] = v;
    }

    const float* r0 = &ws[( 0 + (n0 - ub)) * 1024];
    const float* r1 = &ws[(16 + (n0 - ub)) * 1024];
    const float* r2 = &ws[(32 + (n0 - ub)) * 1024];
    const float* r3 = Wh + (size_t)(3072 + n0) * 1024;
    const float* r4 = r0 + 1024;
    const float* r5 = r1 + 1024;
    const float* r6 = r2 + 1024;
    const float* r7 = r3 + 1024;

    const int u    = lane >> 3;
    const int b    = lane & 7;
    const int p    = b >> 1;
    const int half = b & 1;
    const int n    = n0 + u;
    const int lbmy = lengths[b];
    const int lb0 = lengths[0], lb2 = lengths[2];
    const int lb4 = lengths[4], lb6 = lengths[6];
    float hreg = 0.f, creg = 0.f;

    if (lane < 16) g_hpair[0][dir][p][n][half] = 0.f;

    dir_sync(dir, myblk, 1u);

    for (int t = 0; t < 512; ++t){
        const int rbuf = t & 1, wbuf = rbuf ^ 1;
        const int pact = (t < lb0) + (t < lb2) + (t < lb4) + (t < lb6);

        float q0 = 0.f, q1 = 0.f, q2 = 0.f, q3 = 0.f;
        const bool act = (lane < 16) && (t < lbmy);
        int pos = 0;
        if (act){
            pos = dir ? (lbmy - 1 - t) : t;
            const float* Gp = &g_G[dir][(b << 9) + pos][0];
            q0 = Gp[n]; q1 = Gp[1024 + n]; q2 = Gp[2048 + n]; q3 = Gp[3072 + n];
        }

        {
            const float4* src = (const float4*)&g_hpair[rbuf][dir][0][0][0];
            float4* dst = (float4*)hs;
            const int tot = pact << 9;
            for (int idx = tid; idx < tot; idx += 256)
                dst[idx] = __ldcg(src + idx);
        }
        __syncthreads();

        float* hb_w = &g_hpair[wbuf][dir][p][n][half];
        float* ho_w = &g_hout[dir][b][pos][n];

        switch (pact){
        case 4: lstm_step_t<4>(r0,r1,r2,r3,r4,r5,r6,r7, hs, lane, u, p, half, act,
                               q0,q1,q2,q3, hb_w, ho_w, creg, hreg); break;
        case 3: lstm_step_t<3>(r0,r1,r2,r3,r4,r5,r6,r7, hs, lane, u, p, half, act,
                               q0,q1,q2,q3, hb_w, ho_w, creg, hreg); break;
        case 2: lstm_step_t<2>(r0,r1,r2,r3,r4,r5,r6,r7, hs, lane, u, p, half, act,
                               q0,q1,q2,q3, hb_w, ho_w, creg, hreg); break;
        default: lstm_step_t<1>(r0,r1,r2,r3,r4,r5,r6,r7, hs, lane, u, p, half, act,
                               q0,q1,q2,q3, hb_w, ho_w, creg, hreg); break;
        }

        if (t < 511) dir_sync(dir, myblk, (unsigned)(t + 2));
    }
}

// ---------------- Phase C1: emissions ----------------
__global__ void emit_kernel(const int* __restrict__ lengths,
                            const float* __restrict__ We,
                            const float* __restrict__ be)
{
    const int t = blockIdx.x, b = blockIdx.y;
    if (t >= lengths[b]) return;
    __shared__ float h[2048];
    const int tid = threadIdx.x;
    const float* hf = &g_hout[0][b][t][0];
    const float* hb = &g_hout[1][b][t][0];
    for (int j = tid; j < 1024; j += 128){
        h[j]        = hf[j];
        h[1024 + j] = hb[j];
    }
    __syncthreads();
    const int k = tid >> 3, sub = tid & 7;
    const float* wk = We + (k << 11);
    float s = 0.f;
    for (int j = (sub << 2); j < 2048; j += 32){
        float4 wv = *(const float4*)(wk + j);
        float4 hv = *(const float4*)(&h[j]);
        s += wv.x * hv.x + wv.y * hv.y + wv.z * hv.z + wv.w * hv.w;
    }
    s += __shfl_xor_sync(0xffffffffu, s, 4);
    s += __shfl_xor_sync(0xffffffffu, s, 2);
    s += __shfl_xor_sync(0xffffffffu, s, 1);
    if (sub == 0) g_emit[b][t][k] = s + be[k];
}

// ---------------- Phase C2: CRF gold score + forward algorithm ----------------
__global__ void crf_kernel(const int* __restrict__ tags,
                           const int* __restrict__ lengths,
                           const float* __restrict__ trans,
                           float* __restrict__ out)
{
    __shared__ float T[16][16];
    const int tid = threadIdx.x;
    T[tid >> 4][tid & 15] = trans[tid];
    __syncthreads();

    const int b = tid >> 5, lane = tid & 31;
    const int lb = lengths[b];
    const int* tg = tags + (b << 9);

    float sc = 0.f;
    for (int tt = lane; tt < lb; tt += 32){
        sc += g_emit[b][tt][tg[tt]];
        if (tt >= 1) sc += T[tg[tt - 1]][tg[tt]];
    }
#pragma unroll
    for (int o = 16; o; o >>= 1) sc += __shfl_xor_sync(0xffffffffu, sc, o);

    const int j = lane & 15;
    float d = (lane < 16) ? g_emit[b][0][j] : -3e38f;
    for (int tt = 1; tt < lb; ++tt){
        float v[16];
        float mx = -3e38f;
#pragma unroll
        for (int i = 0; i < 16; ++i){
            float di = __shfl_sync(0xffffffffu, d, i);
            v[i] = di + T[i][j];
            mx = fmaxf(mx, v[i]);
        }
        float ssum = 0.f;
#pragma unroll
        for (int i = 0; i < 16; ++i) ssum += __expf(v[i] - mx);
        float nd = mx + __logf(ssum) + g_emit[b][tt][j];
        if (lane < 16) d = nd;
    }

    float mz = d;
#pragma unroll
    for (int o = 8; o; o >>= 1) mz = fmaxf(mz, __shfl_xor_sync(0xffffffffu, mz, o));
    float zs = __expf(d - mz);
#pragma unroll
    for (int o = 8; o; o >>= 1) zs += __shfl_xor_sync(0xffffffffu, zs, o);
    float logZ = mz + __logf(zs);

    if (lane == 0) out[b] = logZ - sc;
}

// ---------------- launch ----------------
extern "C" void kernel_launch(void* const* d_in, const int* in_sizes, int n_in,
                              void* d_out, int out_size)
{
    (void)in_sizes; (void)n_in; (void)out_size;
    const float* x    = (const float*)d_in[0];
    const int*   tags = (const int*)  d_in[1];
    const int*   lens = (const int*)  d_in[2];
    const float* Wihf = (const float*)d_in[3];
    const float* Whhf = (const float*)d_in[4];
    const float* bf_  = (const float*)d_in[5];
    const float* Wihb = (const float*)d_in[6];
    const float* Whhb = (const float*)d_in[7];
    const float* bb_  = (const float*)d_in[8];
    const float* We   = (const float*)d_in[9];
    const float* be   = (const float*)d_in[10];
    const float* tr   = (const float*)d_in[11];
    float* out = (float*)d_out;

    cudaFuncSetAttribute(lstm_persist,
                         cudaFuncAttributeMaxDynamicSharedMemorySize, SMEM_PERSIST);

    init_bar<<<1, 256>>>();
    proj_gemm_tc<<<dim3(32, 32, 2), 256>>>(x, Wihf, bf_, Wihb, bb_);
    lstm_persist<<<128, 256, SMEM_PERSIST>>>(Whhf, Whhb, lens);
    emit_kernel<<<dim3(512, 8), 128>>>(lens, We, be);
    crf_kernel<<<1, 256>>>(tags, lens, tr, out);
}

// round 13
// speedup vs baseline: 2.3470x; 1.0201x over previous
#include <cuda_runtime.h>

// B=8, L=512, E=H=1024, K=16, 4H=4096
typedef unsigned long long u64;

// ---------------- scratch (static __device__; no allocations) ----------------
__device__ float g_G[2][4096][4096];          // input projections + bias
__device__ float g_hpair[2][2][4][1024][2];   // h double-buffered, batch-PAIR interleaved
__device__ float g_hout[2][8][512][1024];     // h outputs at original positions
__device__ float g_emit[8][512][16];          // emissions
__device__ unsigned g_flag[2][64][32];        // distributed barrier flags (128B padded)

// ---------------- packed f32x2 helpers ----------------
__device__ __forceinline__ u64 pack1(float x){
    u64 r;
    asm("mov.b64 %0, {%1, %1};" : "=l"(r) : "r"(__float_as_uint(x)));
    return r;
}
__device__ __forceinline__ void unpack2(u64 v, float &x, float &y){
    unsigned a, b;
    asm("mov.b64 {%0, %1}, %2;" : "=r"(a), "=r"(b) : "l"(v));
    x = __uint_as_float(a); y = __uint_as_float(b);
}
__device__ __forceinline__ void ffma2(u64 &acc, u64 a, u64 b){
    asm("fma.rn.f32x2 %0, %1, %2, %0;" : "+l"(acc) : "l"(a), "l"(b));
}
__device__ __forceinline__ u64 addf2(u64 a, u64 b){
    u64 r;
    asm("add.rn.f32x2 %0, %1, %2;" : "=l"(r) : "l"(a), "l"(b));
    return r;
}
__device__ __forceinline__ u64 shfl_xor_u64(u64 v, int m){
    unsigned lo = (unsigned)(v & 0xffffffffull);
    unsigned hi = (unsigned)(v >> 32);
    lo = __shfl_xor_sync(0xffffffffu, lo, m);
    hi = __shfl_xor_sync(0xffffffffu, hi, m);
    return ((u64)hi << 32) | (u64)lo;
}
__device__ __forceinline__ u64 shfl_idx_u64(u64 v, int src){
    unsigned lo = (unsigned)(v & 0xffffffffull);
    unsigned hi = (unsigned)(v >> 32);
    lo = __shfl_sync(0xffffffffu, lo, src);
    hi = __shfl_sync(0xffffffffu, hi, src);
    return ((u64)hi << 32) | (u64)lo;
}
__device__ __forceinline__ float fast_sigmoid(float x){
    return 1.f / (1.f + __expf(-x));
}
__device__ __forceinline__ float fast_tanh(float x){
    return 1.f - 2.f / (__expf(2.f * x) + 1.f);   // stable at both infinities
}

__global__ void init_bar(){
    int i = threadIdx.x;
    unsigned* f = &g_flag[0][0][0];
    for (int idx = i; idx < 2 * 64 * 32; idx += 256) f[idx] = 0u;
}

// ---------------- Phase A: G = X @ W_ih^T + b via tf32 tensor cores ----------------
__device__ __forceinline__ void mma_tf32(
    float &d0, float &d1, float &d2, float &d3,
    unsigned a0, unsigned a1, unsigned a2, unsigned a3,
    unsigned b0, unsigned b1)
{
    asm volatile(
        "mma.sync.aligned.m16n8k8.row.col.f32.tf32.tf32.f32 "
        "{%0,%1,%2,%3}, {%4,%5,%6,%7}, {%8,%9}, {%0,%1,%2,%3};"
        : "+f"(d0), "+f"(d1), "+f"(d2), "+f"(d3)
        : "r"(a0), "r"(a1), "r"(a2), "r"(a3), "r"(b0), "r"(b1));
}

__global__ __launch_bounds__(256) void proj_gemm_tc(
    const float* __restrict__ x,
    const float* __restrict__ Wf, const float* __restrict__ bf,
    const float* __restrict__ Wb, const float* __restrict__ bb)
{
    __shared__ float As[128 * 20];
    __shared__ float Bs[128 * 20];
    const int dir = blockIdx.z;
    const float* W    = dir ? Wb : Wf;
    const float* bias = dir ? bb : bf;
    const int tid = threadIdx.x;
    const int mBase = blockIdx.y << 7;
    const int nBase = blockIdx.x << 7;
    const int warp = tid >> 5, lane = tid & 31;
    const int wm = warp & 1;
    const int wn = warp >> 1;
    const int lr = lane >> 2;
    const int lc = lane & 3;

    const int grow = tid >> 1;
    const int gk   = (tid & 1) << 3;

    const float* xp = x + (size_t)(mBase + grow) * 1024 + gk;
    const float* wp = W + (size_t)(nBase + grow) * 1024 + gk;

    float acc[4][4][4];
#pragma unroll
    for (int i = 0; i < 4; ++i)
#pragma unroll
        for (int j = 0; j < 4; ++j)
#pragma unroll
            for (int c = 0; c < 4; ++c) acc[i][j][c] = 0.f;

    float4 ax0 = *(const float4*)(xp);
    float4 ax1 = *(const float4*)(xp + 4);
    float4 bx0 = *(const float4*)(wp);
    float4 bx1 = *(const float4*)(wp + 4);

    for (int kt = 0; kt < 64; ++kt){
        __syncthreads();
        *(float4*)&As[grow * 20 + gk]     = ax0;
        *(float4*)&As[grow * 20 + gk + 4] = ax1;
        *(float4*)&Bs[grow * 20 + gk]     = bx0;
        *(float4*)&Bs[grow * 20 + gk + 4] = bx1;
        __syncthreads();
        if (kt < 63){
            ax0 = *(const float4*)(xp + (kt + 1) * 16);
            ax1 = *(const float4*)(xp + (kt + 1) * 16 + 4);
            bx0 = *(const float4*)(wp + (kt + 1) * 16);
            bx1 = *(const float4*)(wp + (kt + 1) * 16 + 4);
        }
#pragma unroll
        for (int k8 = 0; k8 < 2; ++k8){
            const int kb = (k8 << 3) + lc;
            unsigned af[4][4];
#pragma unroll
            for (int mt = 0; mt < 4; ++mt){
                const int m0 = (wm << 6) + (mt << 4);
                af[mt][0] = __float_as_uint(As[(m0 + lr)     * 20 + kb]);
                af[mt][1] = __float_as_uint(As[(m0 + lr + 8) * 20 + kb]);
                af[mt][2] = __float_as_uint(As[(m0 + lr)     * 20 + kb + 4]);
                af[mt][3] = __float_as_uint(As[(m0 + lr + 8) * 20 + kb + 4]);
            }
            unsigned bfr[4][2];
#pragma unroll
            for (int nt = 0; nt < 4; ++nt){
                const int n0 = (wn << 5) + (nt << 3);
                bfr[nt][0] = __float_as_uint(Bs[(n0 + lr) * 20 + kb]);
                bfr[nt][1] = __float_as_uint(Bs[(n0 + lr) * 20 + kb + 4]);
            }
#pragma unroll
            for (int mt = 0; mt < 4; ++mt)
#pragma unroll
                for (int nt = 0; nt < 4; ++nt)
                    mma_tf32(acc[mt][nt][0], acc[mt][nt][1],
                             acc[mt][nt][2], acc[mt][nt][3],
                             af[mt][0], af[mt][1], af[mt][2], af[mt][3],
                             bfr[nt][0], bfr[nt][1]);
        }
    }

#pragma unroll
    for (int nt = 0; nt < 4; ++nt){
        const int gcol = nBase + (wn << 5) + (nt << 3) + (lc << 1);
        float2 bv = *(const float2*)(bias + gcol);
#pragma unroll
        for (int mt = 0; mt < 4; ++mt){
            const int grow0 = mBase + (wm << 6) + (mt << 4) + lr;
            float2 r0 = make_float2(acc[mt][nt][0] + bv.x, acc[mt][nt][1] + bv.y);
            float2 r1 = make_float2(acc[mt][nt][2] + bv.x, acc[mt][nt][3] + bv.y);
            *(float2*)(&g_G[dir][grow0][gcol])     = r0;
            *(float2*)(&g_G[dir][grow0 + 8][gcol]) = r1;
        }
    }
}

// ---------------- Phase B: persistent bidirectional LSTM ----------------
// 128 blocks x 512 threads (16 warps). Block: one dir, 16 units (1/warp).
// Gates i,f,g in smem fp32; gate-o rows stream from L2.
// Barrier: producer-targeted spin (each thread waits exactly on the block
// that writes the h chunk it will stage).
#define SMEM_PERSIST (48*1024*4 + 4*1024*8)   // 229376 B

template<int PACT>
__device__ __forceinline__ void lstm_step_t(
    const float* __restrict__ wi, const float* __restrict__ wf_,
    const float* __restrict__ wg, const float* __restrict__ wo,
    const float2* __restrict__ hs, int lane,
    int p, int half, bool act,
    float q0, float q1, float q2, float q3,
    float* hb_w, float* ho_w, float &creg, float &hreg)
{
    u64 acc[4][PACT];
#pragma unroll
    for (int r = 0; r < 4; ++r)
#pragma unroll
        for (int pp = 0; pp < PACT; ++pp) acc[r][pp] = 0ull;

    const float* const wr[4] = {wi, wf_, wg, wo};

#pragma unroll 2
    for (int c = 0; c < 8; ++c){
        const int k = (c << 7) + (lane << 2);
        u64 hk[PACT][4];
#pragma unroll
        for (int pp = 0; pp < PACT; ++pp){
            ulonglong2 A = *(const ulonglong2*)&hs[(pp << 10) + k];
            ulonglong2 B = *(const ulonglong2*)&hs[(pp << 10) + k + 2];
            hk[pp][0] = A.x; hk[pp][1] = A.y; hk[pp][2] = B.x; hk[pp][3] = B.y;
        }
#pragma unroll
        for (int r = 0; r < 4; ++r){
            float4 wv = *(const float4*)(wr[r] + k);
            u64 s0 = pack1(wv.x), s1 = pack1(wv.y);
            u64 s2 = pack1(wv.z), s3 = pack1(wv.w);
#pragma unroll
            for (int pp = 0; pp < PACT; ++pp){
                ffma2(acc[r][pp], s0, hk[pp][0]);
                ffma2(acc[r][pp], s1, hk[pp][1]);
                ffma2(acc[r][pp], s2, hk[pp][2]);
                ffma2(acc[r][pp], s3, hk[pp][3]);
            }
        }
    }

    // ---- reduce-scatter, V = 4*PACT values (a = pp*4 + r) ----
    constexpr int V = (PACT == 3) ? 16 : 4 * PACT;   // pad pact3 to 16
    u64 red;
    if (V == 16){
        u64 A[16];
#pragma unroll
        for (int pp = 0; pp < 4; ++pp)
#pragma unroll
            for (int r = 0; r < 4; ++r)
                A[(pp << 2) + r] = (pp < PACT) ? acc[r][pp < PACT ? pp : 0] : 0ull;
        u64 B8[8];
#pragma unroll
        for (int i = 0; i < 8; ++i){
            u64 send = (lane & 16) ? A[i] : A[i + 8];
            u64 recv = shfl_xor_u64(send, 16);
            u64 keep = (lane & 16) ? A[i + 8] : A[i];
            B8[i] = addf2(keep, recv);
        }
        u64 B4[4];
#pragma unroll
        for (int i = 0; i < 4; ++i){
            u64 send = (lane & 8) ? B8[i] : B8[i + 4];
            u64 recv = shfl_xor_u64(send, 8);
            u64 keep = (lane & 8) ? B8[i + 4] : B8[i];
            B4[i] = addf2(keep, recv);
        }
        u64 B2[2];
#pragma unroll
        for (int i = 0; i < 2; ++i){
            u64 send = (lane & 4) ? B4[i] : B4[i + 2];
            u64 recv = shfl_xor_u64(send, 4);
            u64 keep = (lane & 4) ? B4[i + 2] : B4[i];
            B2[i] = addf2(keep, recv);
        }
        u64 B1;
        {
            u64 send = (lane & 2) ? B2[0] : B2[1];
            u64 recv = shfl_xor_u64(send, 2);
            u64 keep = (lane & 2) ? B2[1] : B2[0];
            B1 = addf2(keep, recv);
        }
        red = addf2(B1, shfl_xor_u64(B1, 1));
    } else if (V == 8){
        u64 A[8];
#pragma unroll
        for (int pp = 0; pp < 2; ++pp)
#pragma unroll
            for (int r = 0; r < 4; ++r)
                A[(pp << 2) + r] = acc[r][pp < PACT ? pp : 0];   // PACT==2 exact
        u64 B4[4];
#pragma unroll
        for (int i = 0; i < 4; ++i){
            u64 send = (lane & 16) ? A[i] : A[i + 4];
            u64 recv = shfl_xor_u64(send, 16);
            u64 keep = (lane & 16) ? A[i + 4] : A[i];
            B4[i] = addf2(keep, recv);
        }
        u64 B2[2];
#pragma unroll
        for (int i = 0; i < 2; ++i){
            u64 send = (lane & 8) ? B4[i] : B4[i + 2];
            u64 recv = shfl_xor_u64(send, 8);
            u64 keep = (lane & 8) ? B4[i + 2] : B4[i];
            B2[i] = addf2(keep, recv);
        }
        u64 B1;
        {
            u64 send = (lane & 4) ? B2[0] : B2[1];
            u64 recv = shfl_xor_u64(send, 4);
            u64 keep = (lane & 4) ? B2[1] : B2[0];
            B1 = addf2(keep, recv);
        }
        B1 = addf2(B1, shfl_xor_u64(B1, 2));
        red = addf2(B1, shfl_xor_u64(B1, 1));
    } else {  // V == 4 (PACT == 1)
        u64 A[4];
#pragma unroll
        for (int r = 0; r < 4; ++r) A[r] = acc[r][0];
        u64 B2[2];
#pragma unroll
        for (int i = 0; i < 2; ++i){
            u64 send = (lane & 16) ? A[i] : A[i + 2];
            u64 recv = shfl_xor_u64(send, 16);
            u64 keep = (lane & 16) ? A[i + 2] : A[i];
            B2[i] = addf2(keep, recv);
        }
        u64 B1;
        {
            u64 send = (lane & 8) ? B2[0] : B2[1];
            u64 recv = shfl_xor_u64(send, 8);
            u64 keep = (lane & 8) ? B2[1] : B2[0];
            B1 = addf2(keep, recv);
        }
        B1 = addf2(B1, shfl_xor_u64(B1, 4));
        B1 = addf2(B1, shfl_xor_u64(B1, 2));
        red = addf2(B1, shfl_xor_u64(B1, 1));
    }

    // gather: value a lives on lane a*(32/V); lane b<8 needs a = p*4 + g
    constexpr int GSTRIDE = 32 / V;
    const int pc = (p < PACT) ? p : 0;
    u64 G0 = shfl_idx_u64(red, ((pc << 2) + 0) * GSTRIDE);
    u64 G1 = shfl_idx_u64(red, ((pc << 2) + 1) * GSTRIDE);
    u64 G2 = shfl_idx_u64(red, ((pc << 2) + 2) * GSTRIDE);
    u64 G3 = shfl_idx_u64(red, ((pc << 2) + 3) * GSTRIDE);

    if (lane < 8){
        float lo, hi, gs0, gs1, gs2, gs3;
        unpack2(G0, lo, hi); gs0 = half ? hi : lo;
        unpack2(G1, lo, hi); gs1 = half ? hi : lo;
        unpack2(G2, lo, hi); gs2 = half ? hi : lo;
        unpack2(G3, lo, hi); gs3 = half ? hi : lo;
        if (act){
            float gi = gs0 + q0;
            float gf = gs1 + q1;
            float gg = gs2 + q2;
            float go = gs3 + q3;
            float si = fast_sigmoid(gi);
            float sf = fast_sigmoid(gf);
            float tg = fast_tanh(gg);
            float so = fast_sigmoid(go);
            creg = sf * creg + si * tg;
            hreg = so * fast_tanh(creg);
            *ho_w = hreg;
        }
        *hb_w = hreg;   // carry-forward when masked
    }
}

__global__ __launch_bounds__(512) void lstm_persist(
    const float* __restrict__ Whf, const float* __restrict__ Whb,
    const int* __restrict__ lengths)
{
    extern __shared__ char smraw[];
    float*  ws = (float*)smraw;                     // [48][1024]: gates i,f,g x 16 units
    float2* hs = (float2*)(smraw + 48*1024*4);      // [4][1024]

    const int blk = blockIdx.x;
    const int dir = blk >> 6;
    const int myblk = blk & 63;
    const int ub  = myblk << 4;
    const float* Wh = dir ? Whb : Whf;
    const int tid  = threadIdx.x;
    const int w    = tid >> 5;        // warp 0..15 -> unit
    const int lane = tid & 31;
    const int n    = ub + w;

    // preload 48 weight rows (gates i,f,g for all 16 units)
    for (int i = tid; i < 48 * 256; i += 512){
        int lr = i >> 8, q = (i & 255) << 2;
        int grow = ((lr >> 4) << 10) + ub + (lr & 15);
        float4 v = *(const float4*)(Wh + (size_t)grow * 1024 + q);
        *(float4*)&ws[lr * 1024 + q] = v;
    }

    const float* wi_ = &ws[( 0 + w) * 1024];
    const float* wf2 = &ws[(16 + w) * 1024];
    const float* wg_ = &ws[(32 + w) * 1024];
    const float* wo_ = Wh + (size_t)(3072 + n) * 1024;

    const int b    = lane & 7;
    const int p    = b >> 1;
    const int half = b & 1;
    const int lbmy = lengths[b];
    const int lb0 = lengths[0], lb2 = lengths[2];
    const int lb4 = lengths[4], lb6 = lengths[6];
    float hreg = 0.f, creg = 0.f;

    // producer block feeding MY staging chunks: float4 idx = tid (+512k) covers
    // units n = (2*idx)&1023 .. +1 -> producer = (idx>>3)&63 = tid>>3 (same for all k)
    const int prodblk = (tid & 511) >> 3;
    const unsigned* myflag = &g_flag[dir][prodblk][0];

    if (lane < 8) g_hpair[0][dir][p][n][half] = 0.f;

    // initial barrier (target 1)
    __syncthreads();
    if (tid == 0){
        asm volatile("st.release.gpu.global.u32 [%0], %1;"
                     :: "l"(&g_flag[dir][myblk][0]), "r"(1u) : "memory");
    }
    {
        unsigned v;
        do {
            asm volatile("ld.acquire.gpu.global.u32 %0, [%1];"
                         : "=r"(v) : "l"(myflag) : "memory");
        } while (v < 1u);
    }

    for (int t = 0; t < 512; ++t){
        const int rbuf = t & 1, wbuf = rbuf ^ 1;
        const int pact = (t < lb0) + (t < lb2) + (t < lb4) + (t < lb6);

        float q0 = 0.f, q1 = 0.f, q2 = 0.f, q3 = 0.f;
        const bool act = (lane < 8) && (t < lbmy);
        int pos = 0;
        if (act){
            pos = dir ? (lbmy - 1 - t) : t;
            const float* Gp = &g_G[dir][(b << 9) + pos][0];
            q0 = Gp[n]; q1 = Gp[1024 + n]; q2 = Gp[2048 + n]; q3 = Gp[3072 + n];
        }

        // stage active batch-pair h from L2 (producer flag already observed)
        {
            const float4* src = (const float4*)&g_hpair[rbuf][dir][0][0][0];
            float4* dst = (float4*)hs;
            const int tot = pact << 9;
            for (int idx = tid; idx < tot; idx += 512)
                dst[idx] = __ldcg(src + idx);
        }
        __syncthreads();   // all threads passed spins -> all 64 producers >= t+1 done

        float* hb_w = &g_hpair[wbuf][dir][p][n][half];
        float* ho_w = &g_hout[dir][b][pos][n];

        switch (pact){
        case 4: lstm_step_t<4>(wi_, wf2, wg_, wo_, hs, lane, p, half, act,
                               q0,q1,q2,q3, hb_w, ho_w, creg, hreg); break;
        case 3: lstm_step_t<3>(wi_, wf2, wg_, wo_, hs, lane, p, half, act,
                               q0,q1,q2,q3, hb_w, ho_w, creg, hreg); break;
        case 2: lstm_step_t<2>(wi_, wf2, wg_, wo_, hs, lane, p, half, act,
                               q0,q1,q2,q3, hb_w, ho_w, creg, hreg); break;
        default: lstm_step_t<1>(wi_, wf2, wg_, wo_, hs, lane, p, half, act,
                               q0,q1,q2,q3, hb_w, ho_w, creg, hreg); break;
        }

        if (t < 511){
            const unsigned target = (unsigned)(t + 2);
            __syncthreads();   // all h writes of this block done
            if (tid == 0){
                asm volatile("st.release.gpu.global.u32 [%0], %1;"
                             :: "l"(&g_flag[dir][myblk][0]), "r"(target) : "memory");
            }
            unsigned v;
            do {
                asm volatile("ld.acquire.gpu.global.u32 %0, [%1];"
                             : "=r"(v) : "l"(myflag) : "memory");
            } while (v < target);
        }
    }
}

// ---------------- Phase C1: emissions ----------------
__global__ void emit_kernel(const int* __restrict__ lengths,
                            const float* __restrict__ We,
                            const float* __restrict__ be)
{
    const int t = blockIdx.x, b = blockIdx.y;
    if (t >= lengths[b]) return;
    __shared__ float h[2048];
    const int tid = threadIdx.x;
    const float* hf = &g_hout[0][b][t][0];
    const float* hb = &g_hout[1][b][t][0];
    for (int j = tid; j < 1024; j += 128){
        h[j]        = hf[j];
        h[1024 + j] = hb[j];
    }
    __syncthreads();
    const int k = tid >> 3, sub = tid & 7;
    const float* wk = We + (k << 11);
    float s = 0.f;
    for (int j = (sub << 2); j < 2048; j += 32){
        float4 wv = *(const float4*)(wk + j);
        float4 hv = *(const float4*)(&h[j]);
        s += wv.x * hv.x + wv.y * hv.y + wv.z * hv.z + wv.w * hv.w;
    }
    s += __shfl_xor_sync(0xffffffffu, s, 4);
    s += __shfl_xor_sync(0xffffffffu, s, 2);
    s += __shfl_xor_sync(0xffffffffu, s, 1);
    if (sub == 0) g_emit[b][t][k] = s + be[k];
}

// ---------------- Phase C2: CRF gold score + forward algorithm ----------------
__global__ void crf_kernel(const int* __restrict__ tags,
                           const int* __restrict__ lengths,
                           const float* __restrict__ trans,
                           float* __restrict__ out)
{
    __shared__ float T[16][16];
    const int tid = threadIdx.x;
    T[tid >> 4][tid & 15] = trans[tid];
    __syncthreads();

    const int b = tid >> 5, lane = tid & 31;
    const int lb = lengths[b];
    const int* tg = tags + (b << 9);

    float sc = 0.f;
    for (int tt = lane; tt < lb; tt += 32){
        sc += g_emit[b][tt][tg[tt]];
        if (tt >= 1) sc += T[tg[tt - 1]][tg[tt]];
    }
#pragma unroll
    for (int o = 16; o; o >>= 1) sc += __shfl_xor_sync(0xffffffffu, sc, o);

    const int j = lane & 15;
    float d = (lane < 16) ? g_emit[b][0][j] : -3e38f;
    for (int tt = 1; tt < lb; ++tt){
        float v[16];
        float mx = -3e38f;
#pragma unroll
        for (int i = 0; i < 16; ++i){
            float di = __shfl_sync(0xffffffffu, d, i);
            v[i] = di + T[i][j];
            mx = fmaxf(mx, v[i]);
        }
        float ssum = 0.f;
#pragma unroll
        for (int i = 0; i < 16; ++i) ssum += __expf(v[i] - mx);
        float nd = mx + __logf(ssum) + g_emit[b][tt][j];
        if (lane < 16) d = nd;
    }

    float mz = d;
#pragma unroll
    for (int o = 8; o; o >>= 1) mz = fmaxf(mz, __shfl_xor_sync(0xffffffffu, mz, o));
    float zs = __expf(d - mz);
#pragma unroll
    for (int o = 8; o; o >>= 1) zs += __shfl_xor_sync(0xffffffffu, zs, o);
    float logZ = mz + __logf(zs);

    if (lane == 0) out[b] = logZ - sc;
}

// ---------------- launch ----------------
extern "C" void kernel_launch(void* const* d_in, const int* in_sizes, int n_in,
                              void* d_out, int out_size)
{
    (void)in_sizes; (void)n_in; (void)out_size;
    const float* x    = (const float*)d_in[0];
    const int*   tags = (const int*)  d_in[1];
    const int*   lens = (const int*)  d_in[2];
    const float* Wihf = (const float*)d_in[3];
    const float* Whhf = (const float*)d_in[4];
    const float* bf_  = (const float*)d_in[5];
    const float* Wihb = (const float*)d_in[6];
    const float* Whhb = (const float*)d_in[7];
    const float* bb_  = (const float*)d_in[8];
    const float* We   = (const float*)d_in[9];
    const float* be   = (const float*)d_in[10];
    const float* tr   = (const float*)d_in[11];
    float* out = (float*)d_out;

    cudaFuncSetAttribute(lstm_persist,
                         cudaFuncAttributeMaxDynamicSharedMemorySize, SMEM_PERSIST);

    init_bar<<<1, 256>>>();
    proj_gemm_tc<<<dim3(32, 32, 2), 256>>>(x, Wihf, bf_, Wihb, bb_);
    lstm_persist<<<128, 512, SMEM_PERSIST>>>(Whhf, Whhb, lens);
    emit_kernel<<<dim3(512, 8), 128>>>(lens, We, be);
    crf_kernel<<<1, 256>>>(tags, lens, tr, out);
}

// round 14
// speedup vs baseline: 3.7363x; 1.5920x over previous
#include <cuda_runtime.h>

// B=8, L=512, E=H=1024, K=16, 4H=4096
typedef unsigned long long u64;

// ---------------- scratch (static __device__; no allocations) ----------------
__device__ float g_G[2][4096][4096];                      // input projections + bias
__device__ __align__(16) unsigned short g_hb[2][2][8][1024]; // h double-buffered, bf16 [buf][dir][b][n]
__device__ float g_hout[2][8][512][1024];                 // h outputs at original positions (fp32)
__device__ float g_emit[8][512][16];                      // emissions
__device__ unsigned g_flag[2][64][32];                    // distributed barrier flags (128B padded)

__device__ __forceinline__ float fast_sigmoid(float x){
    return 1.f / (1.f + __expf(-x));
}
__device__ __forceinline__ float fast_tanh(float x){
    return 1.f - 2.f / (__expf(2.f * x) + 1.f);   // stable at both infinities
}
__device__ __forceinline__ unsigned pack_bf16x2(float lo, float hi){
    unsigned r;
    asm("cvt.rn.bf16x2.f32 %0, %1, %2;" : "=r"(r) : "f"(hi), "f"(lo));
    return r;
}
__device__ __forceinline__ unsigned short to_bf16(float x){
    unsigned short h;
    asm("cvt.rn.bf16.f32 %0, %1;" : "=h"(h) : "f"(x));
    return h;
}

__global__ void init_bar(){
    int i = threadIdx.x;
    unsigned* f = &g_flag[0][0][0];
    for (int idx = i; idx < 2 * 64 * 32; idx += 256) f[idx] = 0u;
}

// ---------------- Phase A: G = X @ W_ih^T + b via tf32 tensor cores ----------------
__device__ __forceinline__ void mma_tf32(
    float &d0, float &d1, float &d2, float &d3,
    unsigned a0, unsigned a1, unsigned a2, unsigned a3,
    unsigned b0, unsigned b1)
{
    asm volatile(
        "mma.sync.aligned.m16n8k8.row.col.f32.tf32.tf32.f32 "
        "{%0,%1,%2,%3}, {%4,%5,%6,%7}, {%8,%9}, {%0,%1,%2,%3};"
        : "+f"(d0), "+f"(d1), "+f"(d2), "+f"(d3)
        : "r"(a0), "r"(a1), "r"(a2), "r"(a3), "r"(b0), "r"(b1));
}

__global__ __launch_bounds__(256) void proj_gemm_tc(
    const float* __restrict__ x,
    const float* __restrict__ Wf, const float* __restrict__ bf,
    const float* __restrict__ Wb, const float* __restrict__ bb)
{
    __shared__ float As[128 * 20];
    __shared__ float Bs[128 * 20];
    const int dir = blockIdx.z;
    const float* W    = dir ? Wb : Wf;
    const float* bias = dir ? bb : bf;
    const int tid = threadIdx.x;
    const int mBase = blockIdx.y << 7;
    const int nBase = blockIdx.x << 7;
    const int warp = tid >> 5, lane = tid & 31;
    const int wm = warp & 1;
    const int wn = warp >> 1;
    const int lr = lane >> 2;
    const int lc = lane & 3;

    const int grow = tid >> 1;
    const int gk   = (tid & 1) << 3;

    const float* xp = x + (size_t)(mBase + grow) * 1024 + gk;
    const float* wp = W + (size_t)(nBase + grow) * 1024 + gk;

    float acc[4][4][4];
#pragma unroll
    for (int i = 0; i < 4; ++i)
#pragma unroll
        for (int j = 0; j < 4; ++j)
#pragma unroll
            for (int c = 0; c < 4; ++c) acc[i][j][c] = 0.f;

    float4 ax0 = *(const float4*)(xp);
    float4 ax1 = *(const float4*)(xp + 4);
    float4 bx0 = *(const float4*)(wp);
    float4 bx1 = *(const float4*)(wp + 4);

    for (int kt = 0; kt < 64; ++kt){
        __syncthreads();
        *(float4*)&As[grow * 20 + gk]     = ax0;
        *(float4*)&As[grow * 20 + gk + 4] = ax1;
        *(float4*)&Bs[grow * 20 + gk]     = bx0;
        *(float4*)&Bs[grow * 20 + gk + 4] = bx1;
        __syncthreads();
        if (kt < 63){
            ax0 = *(const float4*)(xp + (kt + 1) * 16);
            ax1 = *(const float4*)(xp + (kt + 1) * 16 + 4);
            bx0 = *(const float4*)(wp + (kt + 1) * 16);
            bx1 = *(const float4*)(wp + (kt + 1) * 16 + 4);
        }
#pragma unroll
        for (int k8 = 0; k8 < 2; ++k8){
            const int kb = (k8 << 3) + lc;
            unsigned af[4][4];
#pragma unroll
            for (int mt = 0; mt < 4; ++mt){
                const int m0 = (wm << 6) + (mt << 4);
                af[mt][0] = __float_as_uint(As[(m0 + lr)     * 20 + kb]);
                af[mt][1] = __float_as_uint(As[(m0 + lr + 8) * 20 + kb]);
                af[mt][2] = __float_as_uint(As[(m0 + lr)     * 20 + kb + 4]);
                af[mt][3] = __float_as_uint(As[(m0 + lr + 8) * 20 + kb + 4]);
            }
            unsigned bfr[4][2];
#pragma unroll
            for (int nt = 0; nt < 4; ++nt){
                const int n0 = (wn << 5) + (nt << 3);
                bfr[nt][0] = __float_as_uint(Bs[(n0 + lr) * 20 + kb]);
                bfr[nt][1] = __float_as_uint(Bs[(n0 + lr) * 20 + kb + 4]);
            }
#pragma unroll
            for (int mt = 0; mt < 4; ++mt)
#pragma unroll
                for (int nt = 0; nt < 4; ++nt)
                    mma_tf32(acc[mt][nt][0], acc[mt][nt][1],
                             acc[mt][nt][2], acc[mt][nt][3],
                             af[mt][0], af[mt][1], af[mt][2], af[mt][3],
                             bfr[nt][0], bfr[nt][1]);
        }
    }

#pragma unroll
    for (int nt = 0; nt < 4; ++nt){
        const int gcol = nBase + (wn << 5) + (nt << 3) + (lc << 1);
        float2 bv = *(const float2*)(bias + gcol);
#pragma unroll
        for (int mt = 0; mt < 4; ++mt){
            const int grow0 = mBase + (wm << 6) + (mt << 4) + lr;
            float2 r0 = make_float2(acc[mt][nt][0] + bv.x, acc[mt][nt][1] + bv.y);
            float2 r1 = make_float2(acc[mt][nt][2] + bv.x, acc[mt][nt][3] + bv.y);
            *(float2*)(&g_G[dir][grow0][gcol])     = r0;
            *(float2*)(&g_G[dir][grow0 + 8][gcol]) = r1;
        }
    }
}

// ---------------- Phase B: persistent bidirectional LSTM (bf16 tensor cores) ----------------
// 128 blocks x 256 threads (8 warps). Block: one dir, 16 units = 64 gate-rows.
// Warp (rt = w&3, kh = w>>2): row-tile rt (16 rows), k-half kh (512 k) -> 32 mma
// m16n8k16 bf16 with fp32 accumulate. Weights preloaded ONCE into smem in exact
// A-fragment layout (one conflict-free LDS.128 per mma). h staged as bf16
// [batch][k] stride 2064B (conflict-free B loads). No shfl reduction: k-sum is
// inside mma accumulation; the 2 k-halves combine via a 4KB smem buffer.
// Row ordering within block: row = (unit%4)*4 + gate, rowtile = unit/4.
#define AFRAG_BYTES 131072          // 4 rt x 64 kt x 32 lanes x 16B
#define HS_OFF      131072
#define HS_STRIDE   2064            // bytes per batch row (1032 bf16): bank-clean
#define HS_BYTES    (8 * HS_STRIDE) // 16512
#define DS_OFF      (HS_OFF + HS_BYTES)          // 147584
#define DS_BYTES    (2 * 4 * 16 * 8 * 4)         // 4096
#define SMEM_PERSIST (DS_OFF + DS_BYTES)         // 151680

__device__ __forceinline__ void mma_bf16(
    float &d0, float &d1, float &d2, float &d3,
    unsigned a0, unsigned a1, unsigned a2, unsigned a3,
    unsigned b0, unsigned b1)
{
    asm volatile(
        "mma.sync.aligned.m16n8k16.row.col.f32.bf16.bf16.f32 "
        "{%0,%1,%2,%3}, {%4,%5,%6,%7}, {%8,%9}, {%0,%1,%2,%3};"
        : "+f"(d0), "+f"(d1), "+f"(d2), "+f"(d3)
        : "r"(a0), "r"(a1), "r"(a2), "r"(a3), "r"(b0), "r"(b1));
}

__global__ __launch_bounds__(256) void lstm_persist(
    const float* __restrict__ Whf, const float* __restrict__ Whb,
    const int* __restrict__ lengths)
{
    extern __shared__ char smem[];

    const int blk = blockIdx.x;
    const int dir = blk >> 6;
    const int myblk = blk & 63;
    const int ub  = myblk << 4;
    const float* Wh = dir ? Whb : Whf;
    const int tid  = threadIdx.x;
    const int w    = tid >> 5;
    const int lane = tid & 31;
    const int rt   = w & 3;          // row-tile 0..3
    const int kh   = w >> 2;         // k-half 0..1

    // ---- preload weights into smem as bf16 A-fragments (one time) ----
    // slot s -> (reg r, lane ln, ktile kt, rowtile rts); each slot = 2 bf16 (k pair)
    for (int s = tid; s < 32768; s += 256){
        int r  = s & 3;
        int ln = (s >> 2) & 31;
        int kt = (s >> 7) & 63;
        int rts = s >> 13;
        int rit  = (ln >> 2) + ((r & 1) << 3);          // row in tile 0..15
        int unit = (rts << 2) + (rit >> 2);
        int gate = rit & 3;
        int k    = (kt << 4) + ((ln & 3) << 1) + ((r >> 1) << 3);
        const float* wrow = Wh + (size_t)((gate << 10) + ub + unit) * 1024 + k;
        ((unsigned*)smem)[(((rts << 6) + kt) << 7) + (ln << 2) + r] =
            pack_bf16x2(wrow[0], wrow[1]);
    }

    // update-thread state (tid < 128): unit = tid>>3, batch = tid&7
    const int uu = tid >> 3;
    const int b  = tid & 7;
    const int lbmy = (tid < 128) ? lengths[b] : 0;
    float creg = 0.f, hreg = 0.f;

    // zero initial h (buffer 0)
    if (tid < 128) g_hb[0][dir][b][ub + uu] = 0;

    // producer block for my staging chunks: idx&127 = tid&127 for all 4 chunks
    const int prodblk = (tid & 127) >> 1;
    const unsigned* myflag = &g_flag[dir][prodblk][0];

    // initial barrier (target 1)
    __syncthreads();
    if (tid == 0){
        asm volatile("st.release.gpu.global.u32 [%0], %1;"
                     :: "l"(&g_flag[dir][myblk][0]), "r"(1u) : "memory");
    }
    {
        unsigned v;
        do {
            asm volatile("ld.acquire.gpu.global.u32 %0, [%1];"
                         : "=r"(v) : "l"(myflag) : "memory");
        } while (v < 1u);
    }

    const uint4* A4 = (const uint4*)smem + ((rt << 6) + (kh << 5)) * 32 + lane;
    const char* hsb = smem + HS_OFF + (lane >> 2) * HS_STRIDE + (kh << 10)
                      + ((lane & 3) << 2);
    float* ds  = (float*)(smem + DS_OFF);

    for (int t = 0; t < 512; ++t){
        const int rbuf = t & 1, wbuf = rbuf ^ 1;

        // prefetch this step's G entries (DRAM latency hidden under staging+mma)
        float q0 = 0.f, q1 = 0.f, q2 = 0.f, q3 = 0.f;
        const bool act = (tid < 128) && (t < lbmy);
        int pos = 0;
        if (act){
            pos = dir ? (lbmy - 1 - t) : t;
            const int n = ub + uu;
            const float* Gp = &g_G[dir][(b << 9) + pos][0];
            q0 = Gp[n]; q1 = Gp[1024 + n]; q2 = Gp[2048 + n]; q3 = Gp[3072 + n];
        }

        // stage h_{t-1} (bf16, 16KB) from L2 into padded smem rows
        {
            const uint4* src = (const uint4*)&g_hb[rbuf][dir][0][0];
#pragma unroll
            for (int j = 0; j < 4; ++j){
                int idx = tid + (j << 8);          // 0..1023
                int bb  = idx >> 7, k16 = idx & 127;
                uint4 v = __ldcg(src + (bb << 7) + k16);
                *(uint4*)(smem + HS_OFF + bb * HS_STRIDE + (k16 << 4)) = v;
            }
        }
        __syncthreads();

        // mma phase: 32 mma per warp, 4 independent accumulators
        float ac[4][4];
#pragma unroll
        for (int j = 0; j < 4; ++j){
            ac[j][0] = 0.f; ac[j][1] = 0.f; ac[j][2] = 0.f; ac[j][3] = 0.f;
        }
#pragma unroll 2
        for (int i8 = 0; i8 < 8; ++i8){
#pragma unroll
            for (int j = 0; j < 4; ++j){
                const int ktl = (i8 << 2) + j;     // 0..31 within k-half
                uint4 a = A4[ktl << 5];
                unsigned b0 = *(const unsigned*)(hsb + (ktl << 5));
                unsigned b1 = *(const unsigned*)(hsb + (ktl << 5) + 16);
                mma_bf16(ac[j][0], ac[j][1], ac[j][2], ac[j][3],
                         a.x, a.y, a.z, a.w, b0, b1);
            }
        }
        float c0 = ac[0][0] + ac[1][0] + ac[2][0] + ac[3][0];
        float c1 = ac[0][1] + ac[1][1] + ac[2][1] + ac[3][1];
        float c2 = ac[0][2] + ac[1][2] + ac[2][2] + ac[3][2];
        float c3 = ac[0][3] + ac[1][3] + ac[2][3] + ac[3][3];

        // write partial D to smem: ds[kh][rt][row][batch]
        {
            float* dw = ds + (kh << 9) + (rt << 7);
            const int g = lane >> 2, tt = lane & 3;
            *(float2*)&dw[(g << 3) + (tt << 1)]       = make_float2(c0, c1);
            *(float2*)&dw[((g + 8) << 3) + (tt << 1)] = make_float2(c2, c3);
        }
        __syncthreads();

        // cell update: thread (unit uu, batch b)
        if (tid < 128){
            const int rtt = uu >> 2;
            const int rb  = ((uu & 3) << 2);
            const float* d0p = ds + (rtt << 7);
            const float* d1p = ds + 512 + (rtt << 7);
            float gi = d0p[((rb + 0) << 3) + b] + d1p[((rb + 0) << 3) + b] + q0;
            float gf = d0p[((rb + 1) << 3) + b] + d1p[((rb + 1) << 3) + b] + q1;
            float gg = d0p[((rb + 2) << 3) + b] + d1p[((rb + 2) << 3) + b] + q2;
            float go = d0p[((rb + 3) << 3) + b] + d1p[((rb + 3) << 3) + b] + q3;
            if (act){
                float si = fast_sigmoid(gi);
                float sf = fast_sigmoid(gf);
                float tg = fast_tanh(gg);
                float so = fast_sigmoid(go);
                creg = sf * creg + si * tg;
                hreg = so * fast_tanh(creg);
                g_hout[dir][b][pos][ub + uu] = hreg;
            }
            g_hb[wbuf][dir][b][ub + uu] = to_bf16(hreg);   // carry when masked
        }

        if (t < 511){
            const unsigned target = (unsigned)(t + 2);
            __syncthreads();   // all h writes of this block done
            if (tid == 0){
                asm volatile("st.release.gpu.global.u32 [%0], %1;"
                             :: "l"(&g_flag[dir][myblk][0]), "r"(target) : "memory");
            }
            unsigned v;
            do {
                asm volatile("ld.acquire.gpu.global.u32 %0, [%1];"
                             : "=r"(v) : "l"(myflag) : "memory");
            } while (v < target);
        }
    }
}

// ---------------- Phase C1: emissions ----------------
__global__ void emit_kernel(const int* __restrict__ lengths,
                            const float* __restrict__ We,
                            const float* __restrict__ be)
{
    const int t = blockIdx.x, b = blockIdx.y;
    if (t >= lengths[b]) return;
    __shared__ float h[2048];
    const int tid = threadIdx.x;
    const float* hf = &g_hout[0][b][t][0];
    const float* hb = &g_hout[1][b][t][0];
    for (int j = tid; j < 1024; j += 128){
        h[j]        = hf[j];
        h[1024 + j] = hb[j];
    }
    __syncthreads();
    const int k = tid >> 3, sub = tid & 7;
    const float* wk = We + (k << 11);
    float s = 0.f;
    for (int j = (sub << 2); j < 2048; j += 32){
        float4 wv = *(const float4*)(wk + j);
        float4 hv = *(const float4*)(&h[j]);
        s += wv.x * hv.x + wv.y * hv.y + wv.z * hv.z + wv.w * hv.w;
    }
    s += __shfl_xor_sync(0xffffffffu, s, 4);
    s += __shfl_xor_sync(0xffffffffu, s, 2);
    s += __shfl_xor_sync(0xffffffffu, s, 1);
    if (sub == 0) g_emit[b][t][k] = s + be[k];
}

// ---------------- Phase C2: CRF gold score + forward algorithm ----------------
__global__ void crf_kernel(const int* __restrict__ tags,
                           const int* __restrict__ lengths,
                           const float* __restrict__ trans,
                           float* __restrict__ out)
{
    __shared__ float T[16][16];
    const int tid = threadIdx.x;
    T[tid >> 4][tid & 15] = trans[tid];
    __syncthreads();

    const int b = tid >> 5, lane = tid & 31;
    const int lb = lengths[b];
    const int* tg = tags + (b << 9);

    float sc = 0.f;
    for (int tt = lane; tt < lb; tt += 32){
        sc += g_emit[b][tt][tg[tt]];
        if (tt >= 1) sc += T[tg[tt - 1]][tg[tt]];
    }
#pragma unroll
    for (int o = 16; o; o >>= 1) sc += __shfl_xor_sync(0xffffffffu, sc, o);

    const int j = lane & 15;
    float d = (lane < 16) ? g_emit[b][0][j] : -3e38f;
    for (int tt = 1; tt < lb; ++tt){
        float v[16];
        float mx = -3e38f;
#pragma unroll
        for (int i = 0; i < 16; ++i){
            float di = __shfl_sync(0xffffffffu, d, i);
            v[i] = di + T[i][j];
            mx = fmaxf(mx, v[i]);
        }
        float ssum = 0.f;
#pragma unroll
        for (int i = 0; i < 16; ++i) ssum += __expf(v[i] - mx);
        float nd = mx + __logf(ssum) + g_emit[b][tt][j];
        if (lane < 16) d = nd;
    }

    float mz = d;
#pragma unroll
    for (int o = 8; o; o >>= 1) mz = fmaxf(mz, __shfl_xor_sync(0xffffffffu, mz, o));
    float zs = __expf(d - mz);
#pragma unroll
    for (int o = 8; o; o >>= 1) zs += __shfl_xor_sync(0xffffffffu, zs, o);
    float logZ = mz + __logf(zs);

    if (lane == 0) out[b] = logZ - sc;
}

// ---------------- launch ----------------
extern "C" void kernel_launch(void* const* d_in, const int* in_sizes, int n_in,
                              void* d_out, int out_size)
{
    (void)in_sizes; (void)n_in; (void)out_size;
    const float* x    = (const float*)d_in[0];
    const int*   tags = (const int*)  d_in[1];
    const int*   lens = (const int*)  d_in[2];
    const float* Wihf = (const float*)d_in[3];
    const float* Whhf = (const float*)d_in[4];
    const float* bf_  = (const float*)d_in[5];
    const float* Wihb = (const float*)d_in[6];
    const float* Whhb = (const float*)d_in[7];
    const float* bb_  = (const float*)d_in[8];
    const float* We   = (const float*)d_in[9];
    const float* be   = (const float*)d_in[10];
    const float* tr   = (const float*)d_in[11];
    float* out = (float*)d_out;

    cudaFuncSetAttribute(lstm_persist,
                         cudaFuncAttributeMaxDynamicSharedMemorySize, SMEM_PERSIST);

    init_bar<<<1, 256>>>();
    proj_gemm_tc<<<dim3(32, 32, 2), 256>>>(x, Wihf, bf_, Wihb, bb_);
    lstm_persist<<<128, 256, SMEM_PERSIST>>>(Whhf, Whhb, lens);
    emit_kernel<<<dim3(512, 8), 128>>>(lens, We, be);
    crf_kernel<<<1, 256>>>(tags, lens, tr, out);
}

// round 15
// speedup vs baseline: 4.2651x; 1.1415x over previous
#include <cuda_runtime.h>

// B=8, L=512, E=H=1024, K=16, 4H=4096
typedef unsigned long long u64;

// ---------------- scratch (static __device__; no allocations) ----------------
__device__ float g_G[2][4096][4096];                      // input projections + bias
__device__ __align__(16) unsigned short g_hb[2][2][8][1024]; // h double-buffered, bf16 [buf][dir][b][n]
__device__ float g_hout[2][8][512][1024];                 // h outputs at original positions (fp32)
__device__ float g_emit[8][512][16];                      // emissions
__device__ unsigned g_flag[2][64][32];                    // arrive-count flags (128B padded)

__device__ __forceinline__ float fast_sigmoid(float x){
    return 1.f / (1.f + __expf(-x));
}
__device__ __forceinline__ float fast_tanh(float x){
    return 1.f - 2.f / (__expf(2.f * x) + 1.f);   // stable at both infinities
}
__device__ __forceinline__ unsigned pack_bf16x2(float lo, float hi){
    unsigned r;
    asm("cvt.rn.bf16x2.f32 %0, %1, %2;" : "=r"(r) : "f"(hi), "f"(lo));
    return r;
}
__device__ __forceinline__ unsigned short to_bf16(float x){
    unsigned short h;
    asm("cvt.rn.bf16.f32 %0, %1;" : "=h"(h) : "f"(x));
    return h;
}

__global__ void init_bar(){
    int i = threadIdx.x;
    unsigned* f = &g_flag[0][0][0];
    for (int idx = i; idx < 2 * 64 * 32; idx += 256) f[idx] = 0u;
}

// ---------------- shared bf16 mma helper ----------------
__device__ __forceinline__ void mma_bf16(
    float &d0, float &d1, float &d2, float &d3,
    unsigned a0, unsigned a1, unsigned a2, unsigned a3,
    unsigned b0, unsigned b1)
{
    asm volatile(
        "mma.sync.aligned.m16n8k16.row.col.f32.bf16.bf16.f32 "
        "{%0,%1,%2,%3}, {%4,%5,%6,%7}, {%8,%9}, {%0,%1,%2,%3};"
        : "+f"(d0), "+f"(d1), "+f"(d2), "+f"(d3)
        : "r"(a0), "r"(a1), "r"(a2), "r"(a3), "r"(b0), "r"(b1));
}

// ---------------- Phase A: G = X @ W_ih^T + b via bf16 tensor cores ----------------
// Block tile 128x128, K-tile 32, 256 threads = 8 warps (2m x 4n), warp tile 64x32.
// fp32 inputs converted to bf16 during smem staging; fp32 accumulate.
// Smem rows: 32 bf16 data + 8 pad = 20 u32 words -> conflict-free fragment LDS.
__global__ __launch_bounds__(256) void proj_gemm_tc(
    const float* __restrict__ x,
    const float* __restrict__ Wf, const float* __restrict__ bf,
    const float* __restrict__ Wb, const float* __restrict__ bb)
{
    __shared__ unsigned As[128 * 20];   // [m][k-pair], stride 20 words
    __shared__ unsigned Bs[128 * 20];   // [n][k-pair]
    const int dir = blockIdx.z;
    const float* W    = dir ? Wb : Wf;
    const float* bias = dir ? bb : bf;
    const int tid = threadIdx.x;
    const int mBase = blockIdx.y << 7;
    const int nBase = blockIdx.x << 7;
    const int warp = tid >> 5, lane = tid & 31;
    const int wm = warp & 1;
    const int wn = warp >> 1;
    const int lr = lane >> 2;
    const int lc = lane & 3;

    const int grow = tid >> 1;           // 0..127
    const int gq   = (tid & 1) << 4;     // k offset 0 or 16

    const float* xp = x + (size_t)(mBase + grow) * 1024 + gq;
    const float* wp = W + (size_t)(nBase + grow) * 1024 + gq;

    float acc[4][4][4];
#pragma unroll
    for (int i = 0; i < 4; ++i)
#pragma unroll
        for (int j = 0; j < 4; ++j)
#pragma unroll
            for (int c = 0; c < 4; ++c) acc[i][j][c] = 0.f;

    float4 ax[4], bx[4];
#pragma unroll
    for (int i = 0; i < 4; ++i){
        ax[i] = *(const float4*)(xp + (i << 2));
        bx[i] = *(const float4*)(wp + (i << 2));
    }

    for (int kt = 0; kt < 32; ++kt){
        __syncthreads();
        {
            unsigned* ad = &As[grow * 20 + ((tid & 1) << 3)];
            unsigned* bd = &Bs[grow * 20 + ((tid & 1) << 3)];
            uint4 pa0 = make_uint4(pack_bf16x2(ax[0].x, ax[0].y), pack_bf16x2(ax[0].z, ax[0].w),
                                   pack_bf16x2(ax[1].x, ax[1].y), pack_bf16x2(ax[1].z, ax[1].w));
            uint4 pa1 = make_uint4(pack_bf16x2(ax[2].x, ax[2].y), pack_bf16x2(ax[2].z, ax[2].w),
                                   pack_bf16x2(ax[3].x, ax[3].y), pack_bf16x2(ax[3].z, ax[3].w));
            uint4 pb0 = make_uint4(pack_bf16x2(bx[0].x, bx[0].y), pack_bf16x2(bx[0].z, bx[0].w),
                                   pack_bf16x2(bx[1].x, bx[1].y), pack_bf16x2(bx[1].z, bx[1].w));
            uint4 pb1 = make_uint4(pack_bf16x2(bx[2].x, bx[2].y), pack_bf16x2(bx[2].z, bx[2].w),
                                   pack_bf16x2(bx[3].x, bx[3].y), pack_bf16x2(bx[3].z, bx[3].w));
            *(uint4*)&ad[0] = pa0;
            *(uint4*)&ad[4] = pa1;
            *(uint4*)&bd[0] = pb0;
            *(uint4*)&bd[4] = pb1;
        }
        __syncthreads();
        if (kt < 31){
#pragma unroll
            for (int i = 0; i < 4; ++i){
                ax[i] = *(const float4*)(xp + (kt + 1) * 32 + (i << 2));
                bx[i] = *(const float4*)(wp + (kt + 1) * 32 + (i << 2));
            }
        }
#pragma unroll
        for (int kg = 0; kg < 2; ++kg){
            const int kw = kg << 3;
            unsigned af[4][4];
#pragma unroll
            for (int mt = 0; mt < 4; ++mt){
                const int m0 = (wm << 6) + (mt << 4);
                af[mt][0] = As[(m0 + lr)     * 20 + kw + lc];
                af[mt][1] = As[(m0 + lr + 8) * 20 + kw + lc];
                af[mt][2] = As[(m0 + lr)     * 20 + kw + 4 + lc];
                af[mt][3] = As[(m0 + lr + 8) * 20 + kw + 4 + lc];
            }
            unsigned bfr[4][2];
#pragma unroll
            for (int nt = 0; nt < 4; ++nt){
                const int n0 = (wn << 5) + (nt << 3);
                bfr[nt][0] = Bs[(n0 + lr) * 20 + kw + lc];
                bfr[nt][1] = Bs[(n0 + lr) * 20 + kw + 4 + lc];
            }
#pragma unroll
            for (int mt = 0; mt < 4; ++mt)
#pragma unroll
                for (int nt = 0; nt < 4; ++nt)
                    mma_bf16(acc[mt][nt][0], acc[mt][nt][1],
                             acc[mt][nt][2], acc[mt][nt][3],
                             af[mt][0], af[mt][1], af[mt][2], af[mt][3],
                             bfr[nt][0], bfr[nt][1]);
        }
    }

#pragma unroll
    for (int nt = 0; nt < 4; ++nt){
        const int gcol = nBase + (wn << 5) + (nt << 3) + (lc << 1);
        float2 bv = *(const float2*)(bias + gcol);
#pragma unroll
        for (int mt = 0; mt < 4; ++mt){
            const int grow0 = mBase + (wm << 6) + (mt << 4) + lr;
            float2 r0 = make_float2(acc[mt][nt][0] + bv.x, acc[mt][nt][1] + bv.y);
            float2 r1 = make_float2(acc[mt][nt][2] + bv.x, acc[mt][nt][3] + bv.y);
            *(float2*)(&g_G[dir][grow0][gcol])     = r0;
            *(float2*)(&g_G[dir][grow0 + 8][gcol]) = r1;
        }
    }
}

// ---------------- Phase B: persistent bidirectional LSTM (bf16 tensor cores) ----------------
// 128 blocks x 256 threads. Block: one dir, 16 units = 64 gate-rows.
// Warp (rt = w&3, kh = w>>2). Weights preloaded ONCE into smem as A-fragments.
// Flags are ARRIVE COUNTS: each of the 4 update warps does red.release.add(1)
// right after storing its h slice -> flag = 4*(steps complete). Consumers wait
// flag >= 4*(t+1) before staging. Two block syncs per step (stage->mma, ds->update).
#define AFRAG_BYTES 131072
#define HS_OFF      131072
#define HS_STRIDE   2064
#define HS_BYTES    (8 * HS_STRIDE)
#define DS_OFF      (HS_OFF + HS_BYTES)
#define DS_BYTES    (2 * 4 * 16 * 8 * 4)
#define SMEM_PERSIST (DS_OFF + DS_BYTES)         // 151680

__global__ __launch_bounds__(256) void lstm_persist(
    const float* __restrict__ Whf, const float* __restrict__ Whb,
    const int* __restrict__ lengths)
{
    extern __shared__ char smem[];

    const int blk = blockIdx.x;
    const int dir = blk >> 6;
    const int myblk = blk & 63;
    const int ub  = myblk << 4;
    const float* Wh = dir ? Whb : Whf;
    const int tid  = threadIdx.x;
    const int w    = tid >> 5;
    const int lane = tid & 31;
    const int rt   = w & 3;          // row-tile 0..3
    const int kh   = w >> 2;         // k-half 0..1

    // ---- preload weights into smem as bf16 A-fragments (one time) ----
    for (int s = tid; s < 32768; s += 256){
        int r  = s & 3;
        int ln = (s >> 2) & 31;
        int kt = (s >> 7) & 63;
        int rts = s >> 13;
        int rit  = (ln >> 2) + ((r & 1) << 3);
        int unit = (rts << 2) + (rit >> 2);
        int gate = rit & 3;
        int k    = (kt << 4) + ((ln & 3) << 1) + ((r >> 1) << 3);
        const float* wrow = Wh + (size_t)((gate << 10) + ub + unit) * 1024 + k;
        ((unsigned*)smem)[(((rts << 6) + kt) << 7) + (ln << 2) + r] =
            pack_bf16x2(wrow[0], wrow[1]);
    }

    // update-thread state (tid < 128): unit = tid>>3, batch = tid&7
    const int uu = tid >> 3;
    const int b  = tid & 7;
    const int lbmy = (tid < 128) ? lengths[b] : 0;
    float creg = 0.f, hreg = 0.f;

    // zero initial h (buffer 0)
    if (tid < 128) g_hb[0][dir][b][ub + uu] = 0;

    // producer block for my staging chunks
    const int prodblk = (tid & 127) >> 1;
    const unsigned* myflag = &g_flag[dir][prodblk][0];
    unsigned* ownflag = &g_flag[dir][myblk][0];

    // publish initial h (counts as "step -1 complete" = 4 arrivals)
    __syncthreads();   // weights staged + initial h written (block-wide ordering)
    if (tid == 0){
        unsigned dummy;
        asm volatile("red.release.gpu.global.add.u32 [%0], %1;"
                     :: "l"(ownflag), "r"(4u) : "memory");
        (void)dummy;
    }

    const uint4* A4 = (const uint4*)smem + ((rt << 6) + (kh << 5)) * 32 + lane;
    const char* hsb = smem + HS_OFF + (lane >> 2) * HS_STRIDE + (kh << 10)
                      + ((lane & 3) << 2);
    float* ds  = (float*)(smem + DS_OFF);

    for (int t = 0; t < 512; ++t){
        const int rbuf = t & 1, wbuf = rbuf ^ 1;

        // prefetch this step's G entries (DRAM latency hidden under spin+staging+mma)
        float q0 = 0.f, q1 = 0.f, q2 = 0.f, q3 = 0.f;
        const bool act = (tid < 128) && (t < lbmy);
        int pos = 0;
        if (act){
            pos = dir ? (lbmy - 1 - t) : t;
            const int n = ub + uu;
            const float* Gp = &g_G[dir][(b << 9) + pos][0];
            q0 = Gp[n]; q1 = Gp[1024 + n]; q2 = Gp[2048 + n]; q3 = Gp[3072 + n];
        }

        // spin until my producer finished step t-1 (h_t published)
        {
            const unsigned target = 4u * (unsigned)(t + 1);
            unsigned v;
            do {
                asm volatile("ld.acquire.gpu.global.u32 %0, [%1];"
                             : "=r"(v) : "l"(myflag) : "memory");
            } while (v < target);
        }

        // stage h_t (bf16, 16KB) from L2 into padded smem rows
        {
            const uint4* src = (const uint4*)&g_hb[rbuf][dir][0][0];
#pragma unroll
            for (int j = 0; j < 4; ++j){
                int idx = tid + (j << 8);
                int bb  = idx >> 7, k16 = idx & 127;
                uint4 v = __ldcg(src + (bb << 7) + k16);
                *(uint4*)(smem + HS_OFF + bb * HS_STRIDE + (k16 << 4)) = v;
            }
        }
        __syncthreads();   // staging complete -> mma may read hs

        // mma phase: 32 mma per warp, 4 independent accumulators
        float ac[4][4];
#pragma unroll
        for (int j = 0; j < 4; ++j){
            ac[j][0] = 0.f; ac[j][1] = 0.f; ac[j][2] = 0.f; ac[j][3] = 0.f;
        }
#pragma unroll 2
        for (int i8 = 0; i8 < 8; ++i8){
#pragma unroll
            for (int j = 0; j < 4; ++j){
                const int ktl = (i8 << 2) + j;
                uint4 a = A4[ktl << 5];
                unsigned b0 = *(const unsigned*)(hsb + (ktl << 5));
                unsigned b1 = *(const unsigned*)(hsb + (ktl << 5) + 16);
                mma_bf16(ac[j][0], ac[j][1], ac[j][2], ac[j][3],
                         a.x, a.y, a.z, a.w, b0, b1);
            }
        }
        float c0 = ac[0][0] + ac[1][0] + ac[2][0] + ac[3][0];
        float c1 = ac[0][1] + ac[1][1] + ac[2][1] + ac[3][1];
        float c2 = ac[0][2] + ac[1][2] + ac[2][2] + ac[3][2];
        float c3 = ac[0][3] + ac[1][3] + ac[2][3] + ac[3][3];

        // write partial D to smem: ds[kh][rt][row][batch]
        {
            float* dw = ds + (kh << 9) + (rt << 7);
            const int g = lane >> 2, tt = lane & 3;
            *(float2*)&dw[(g << 3) + (tt << 1)]       = make_float2(c0, c1);
            *(float2*)&dw[((g + 8) << 3) + (tt << 1)] = make_float2(c2, c3);
        }
        __syncthreads();   // ds complete -> update may read

        // cell update + immediate per-warp publication
        if (tid < 128){
            const int rtt = uu >> 2;
            const int rb  = ((uu & 3) << 2);
            const float* d0p = ds + (rtt << 7);
            const float* d1p = ds + 512 + (rtt << 7);
            float gi = d0p[((rb + 0) << 3) + b] + d1p[((rb + 0) << 3) + b] + q0;
            float gf = d0p[((rb + 1) << 3) + b] + d1p[((rb + 1) << 3) + b] + q1;
            float gg = d0p[((rb + 2) << 3) + b] + d1p[((rb + 2) << 3) + b] + q2;
            float go = d0p[((rb + 3) << 3) + b] + d1p[((rb + 3) << 3) + b] + q3;
            if (act){
                float si = fast_sigmoid(gi);
                float sf = fast_sigmoid(gf);
                float tg = fast_tanh(gg);
                float so = fast_sigmoid(go);
                creg = sf * creg + si * tg;
                hreg = so * fast_tanh(creg);
                g_hout[dir][b][pos][ub + uu] = hreg;
            }
            g_hb[wbuf][dir][b][ub + uu] = to_bf16(hreg);   // carry when masked
            __syncwarp();          // order all 32 lanes' h stores before the add
            if (lane == 0){
                asm volatile("red.release.gpu.global.add.u32 [%0], %1;"
                             :: "l"(ownflag), "r"(1u) : "memory");
            }
        }
    }
}

// ---------------- Phase C1: emissions ----------------
__global__ void emit_kernel(const int* __restrict__ lengths,
                            const float* __restrict__ We,
                            const float* __restrict__ be)
{
    const int t = blockIdx.x, b = blockIdx.y;
    if (t >= lengths[b]) return;
    __shared__ float h[2048];
    const int tid = threadIdx.x;
    const float* hf = &g_hout[0][b][t][0];
    const float* hb = &g_hout[1][b][t][0];
    for (int j = tid; j < 1024; j += 128){
        h[j]        = hf[j];
        h[1024 + j] = hb[j];
    }
    __syncthreads();
    const int k = tid >> 3, sub = tid & 7;
    const float* wk = We + (k << 11);
    float s = 0.f;
    for (int j = (sub << 2); j < 2048; j += 32){
        float4 wv = *(const float4*)(wk + j);
        float4 hv = *(const float4*)(&h[j]);
        s += wv.x * hv.x + wv.y * hv.y + wv.z * hv.z + wv.w * hv.w;
    }
    s += __shfl_xor_sync(0xffffffffu, s, 4);
    s += __shfl_xor_sync(0xffffffffu, s, 2);
    s += __shfl_xor_sync(0xffffffffu, s, 1);
    if (sub == 0) g_emit[b][t][k] = s + be[k];
}

// ---------------- Phase C2: CRF gold score + forward algorithm ----------------
__global__ void crf_kernel(const int* __restrict__ tags,
                           const int* __restrict__ lengths,
                           const float* __restrict__ trans,
                           float* __restrict__ out)
{
    __shared__ float T[16][16];
    const int tid = threadIdx.x;
    T[tid >> 4][tid & 15] = trans[tid];
    __syncthreads();

    const int b = tid >> 5, lane = tid & 31;
    const int lb = lengths[b];
    const int* tg = tags + (b << 9);

    float sc = 0.f;
    for (int tt = lane; tt < lb; tt += 32){
        sc += g_emit[b][tt][tg[tt]];
        if (tt >= 1) sc += T[tg[tt - 1]][tg[tt]];
    }
#pragma unroll
    for (int o = 16; o; o >>= 1) sc += __shfl_xor_sync(0xffffffffu, sc, o);

    const int j = lane & 15;
    float d = (lane < 16) ? g_emit[b][0][j] : -3e38f;
    for (int tt = 1; tt < lb; ++tt){
        float v[16];
        float mx = -3e38f;
#pragma unroll
        for (int i = 0; i < 16; ++i){
            float di = __shfl_sync(0xffffffffu, d, i);
            v[i] = di + T[i][j];
            mx = fmaxf(mx, v[i]);
        }
        float ssum = 0.f;
#pragma unroll
        for (int i = 0; i < 16; ++i) ssum += __expf(v[i] - mx);
        float nd = mx + __logf(ssum) + g_emit[b][tt][j];
        if (lane < 16) d = nd;
    }

    float mz = d;
#pragma unroll
    for (int o = 8; o; o >>= 1) mz = fmaxf(mz, __shfl_xor_sync(0xffffffffu, mz, o));
    float zs = __expf(d - mz);
#pragma unroll
    for (int o = 8; o; o >>= 1) zs += __shfl_xor_sync(0xffffffffu, zs, o);
    float logZ = mz + __logf(zs);

    if (lane == 0) out[b] = logZ - sc;
}

// ---------------- launch ----------------
extern "C" void kernel_launch(void* const* d_in, const int* in_sizes, int n_in,
                              void* d_out, int out_size)
{
    (void)in_sizes; (void)n_in; (void)out_size;
    const float* x    = (const float*)d_in[0];
    const int*   tags = (const int*)  d_in[1];
    const int*   lens = (const int*)  d_in[2];
    const float* Wihf = (const float*)d_in[3];
    const float* Whhf = (const float*)d_in[4];
    const float* bf_  = (const float*)d_in[5];
    const float* Wihb = (const float*)d_in[6];
    const float* Whhb = (const float*)d_in[7];
    const float* bb_  = (const float*)d_in[8];
    const float* We   = (const float*)d_in[9];
    const float* be   = (const float*)d_in[10];
    const float* tr   = (const float*)d_in[11];
    float* out = (float*)d_out;

    cudaFuncSetAttribute(lstm_persist,
                         cudaFuncAttributeMaxDynamicSharedMemorySize, SMEM_PERSIST);

    init_bar<<<1, 256>>>();
    proj_gemm_tc<<<dim3(32, 32, 2), 256>>>(x, Wihf, bf_, Wihb, bb_);
    lstm_persist<<<128, 256, SMEM_PERSIST>>>(Whhf, Whhb, lens);
    emit_kernel<<<dim3(512, 8), 128>>>(lens, We, be);
    crf_kernel<<<1, 256>>>(tags, lens, tr, out);
}